// round 9
// baseline (speedup 1.0000x reference)
#include <cuda_runtime.h>
#include <stdint.h>

#define BATCH 2048
#define EPS 1e-5f

// ---------------- static scratch ----------------
__device__ uint32_t           g_h1[BATCH * 784];        // stem out, 32 ch packed
__device__ unsigned long long g_h2[BATCH * 196];        // block1 out, 64 ch packed (u32 halves)
__device__ uint32_t           g_h3u[BATCH * 49 * 2];    // block2 out, u32 halves
__device__ uint32_t           g_w2p[64 * 12];           // sign(w2), [ch][tap] stride 12
__device__ unsigned long long g_w3p[64 * 10];           // sign(w3), [ch][tap] stride 10
__device__ unsigned long long g_wfcp[256 * 49];         // sign(w_fc)
__device__ float4 g_bn1[32], g_bn4[256];                // (inv, mean, beta, 0)
__device__ int2   g_th2[64], g_th3[64];                 // (integer threshold, sgn)

// ---------------- packing + BN + integer thresholds ----------------
__global__ void pack_kernel(const float* __restrict__ w2, const float* __restrict__ w3,
                            const float* __restrict__ wfc,
                            const float* __restrict__ g1, const float* __restrict__ v1,
                            const float* __restrict__ m1, const float* __restrict__ b1,
                            const float* __restrict__ g2, const float* __restrict__ v2,
                            const float* __restrict__ m2, const float* __restrict__ b2,
                            const float* __restrict__ g3, const float* __restrict__ v3,
                            const float* __restrict__ m3, const float* __restrict__ b3,
                            const float* __restrict__ g4, const float* __restrict__ v4,
                            const float* __restrict__ m4, const float* __restrict__ b4) {
    int idx = blockIdx.x * 256 + threadIdx.x;
    if (idx < 768) {                                   // w2: [64,32,3,3] -> stride 12
        int o = idx / 12, t = idx % 12;
        uint32_t bits = 0;
        if (t < 9)
            for (int c = 0; c < 32; c++)
                bits |= (w2[o * 288 + c * 9 + t] >= 0.f ? 1u : 0u) << c;
        g_w2p[idx] = bits;
    } else if (idx < 1408) {                           // w3: [64,64,3,3] -> stride 10
        int j = idx - 768; int o = j / 10, t = j % 10;
        unsigned long long bits = 0;
        if (t < 9)
            for (int c = 0; c < 64; c++)
                bits |= (unsigned long long)(w3[o * 576 + c * 9 + t] >= 0.f) << c;
        g_w3p[j] = bits;
    } else if (idx < 13952) {                          // w_fc: [256,3136]
        int j = idx - 1408; int o = j / 49, p = j % 49;
        unsigned long long bits = 0;
        for (int c = 0; c < 64; c++)
            bits |= (unsigned long long)(wfc[o * 3136 + c * 49 + p] >= 0.f) << c;
        g_wfcp[j] = bits;
    } else if (idx < 13984) {
        int c = idx - 13952;
        g_bn1[c] = make_float4(g1[c] / sqrtf(v1[c] + EPS), m1[c], b1[c], 0.f);
    } else if (idx < 14240) {
        int c = idx - 13984;
        g_bn4[c] = make_float4(g4[c] / sqrtf(v4[c] + EPS), m4[c], b4[c], 0.f);
    } else if (idx < 14304) {                          // conv2 thresholds (d in [-288,288], even)
        int c = idx - 14240;
        float inv = g2[c] / sqrtf(v2[c] + EPS), m = m2[c], be = b2[c];
        int sgn = (inv >= 0.f) ? 1 : 0;
        int T;
        if (sgn) {
            T = 10000;
            for (int d = -288; d <= 288; d += 2)
                if (((float)d - m) * inv + be >= 0.f) { T = d; break; }
        } else {
            T = -10000;
            for (int d = 288; d >= -288; d -= 2)
                if (((float)d - m) * inv + be >= 0.f) { T = d; break; }
        }
        g_th2[c] = make_int2(T, sgn);
    } else if (idx < 14368) {                          // conv3 thresholds (d in [-576,576], even)
        int c = idx - 14304;
        float inv = g3[c] / sqrtf(v3[c] + EPS), m = m3[c], be = b3[c];
        int sgn = (inv >= 0.f) ? 1 : 0;
        int T;
        if (sgn) {
            T = 10000;
            for (int d = -576; d <= 576; d += 2)
                if (((float)d - m) * inv + be >= 0.f) { T = d; break; }
        } else {
            T = -10000;
            for (int d = 576; d >= -576; d -= 2)
                if (((float)d - m) * inv + be >= 0.f) { T = d; break; }
        }
        g_th3[c] = make_int2(T, sgn);
    }
}

// ---------------- stem: fp32 conv3x3(1->32) + BN + sign, 16 ch/thread ----------------
__global__ void __launch_bounds__(256) stem_kernel(const float* __restrict__ x,
                                                   const float* __restrict__ ws) {
    __shared__ float sw[288];
    __shared__ float4 sbn[32];
    int t = threadIdx.x;
    for (int i = t; i < 288; i += 256) sw[i] = ws[i];
    if (t < 32) sbn[t] = g_bn1[t];
    __syncthreads();

    int idx = blockIdx.x * 256 + t;
    int pix = idx >> 1, half = idx & 1;
    int b = pix / 784, p = pix % 784;
    int y = p / 28, xx = p % 28;
    const float* xb = x + b * 784;

    float win[9];
#pragma unroll
    for (int dy = 0; dy < 3; dy++)
#pragma unroll
        for (int dx = 0; dx < 3; dx++) {
            int yy = y + dy - 1, xc = xx + dx - 1;
            win[dy * 3 + dx] = (yy >= 0 && yy < 28 && xc >= 0 && xc < 28) ? xb[yy * 28 + xc] : 0.f;
        }

    int cb = half * 16;
    uint32_t bits = 0;
#pragma unroll
    for (int ci = 0; ci < 16; ci++) {
        int c = cb + ci;
        float s = 0.f;
#pragma unroll
        for (int k = 0; k < 9; k++) s += sw[c * 9 + k] * win[k];
        float4 bn = sbn[c];
        float v = (s - bn.y) * bn.x + bn.z;
        bits |= (v >= 0.f ? 1u : 0u) << ci;
    }
    ((uint16_t*)g_h1)[pix * 2 + half] = (uint16_t)bits;
}

// ---------------- block1: warp/(img,row,half), sliding register window ----------------
__global__ void __launch_bounds__(256) conv2_kernel() {
    __shared__ uint32_t stile[4][4][28];               // 4 units x 4 input rows x 28 cols
    int tid = threadIdx.x;
    int U0 = blockIdx.x * 4;
    for (int i = tid; i < 448; i += 256) {
        int u = i / 112, r = i % 112, j = r / 28, col = r % 28;
        int U = U0 + u, b = U / 14, oy = U % 14;
        int ir = 2 * oy - 1 + j;
        stile[u][j][col] = (ir >= 0 && ir < 28) ? g_h1[b * 784 + ir * 28 + col] : 0u;
    }
    __syncthreads();

    int w = tid >> 5, lane = tid & 31;
    int u = w >> 1, h = w & 1;
    int U = U0 + u, b = U / 14, oy = U % 14;
    int c = h * 32 + lane;

    uint32_t wt[9];
#pragma unroll
    for (int t = 0; t < 9; t++) wt[t] = g_w2p[c * 12 + t];

    bool e0 = (oy == 0), e1 = (oy == 13);
    int v0 = e0 ? 2 : 3, v1 = e1 ? 2 : 3;
    int pw0 = __popc(wt[0]), pw1 = __popc(wt[1]), pw2 = __popc(wt[2]);
    int pw6 = __popc(wt[6]), pw7 = __popc(wt[7]), pw8 = __popc(wt[8]);
    int Ci0 = 96 * v0 + (e0 ? 2 * (pw0 + pw1 + pw2) : 0);
    int Ci1 = 96 * v1 + (e1 ? 2 * (pw6 + pw7 + pw8) : 0);
    int Cl0 = 64 * v0 + (e0 ? 2 * (pw1 + pw2) : 0);    // X=0 edge (dx in {1,2})
    int Cl1 = 64 * v1 + (e1 ? 2 * (pw7 + pw8) : 0);
    int Cr0 = 64 * v0 + (e0 ? 2 * (pw0 + pw1) : 0);    // X=27 edge (dx in {0,1})
    int Cr1 = 64 * v1 + (e1 ? 2 * (pw6 + pw7) : 0);

    int2 th = g_th2[c];
    int T = th.x;
    bool sgn = th.y != 0;
    const uint32_t* tr = &stile[u][0][0];
    uint32_t* outp = ((uint32_t*)g_h2) + (b * 196 + oy * 14) * 2 + h;

#define TAPS2(cA, cB, cC, nb) do { \
    int a0 = __popc(cA[0] ^ wt[0]) + __popc(cB[0] ^ wt[1]) + __popc(cC[0] ^ wt[2]) \
           + __popc(cA[1] ^ wt[3]) + __popc(cB[1] ^ wt[4]) + __popc(cC[1] ^ wt[5]) \
           + __popc(cA[2] ^ wt[6]) + __popc(cB[2] ^ wt[7]) + __popc(cC[2] ^ wt[8]); \
    int a1 = __popc(cA[1] ^ wt[0]) + __popc(cB[1] ^ wt[1]) + __popc(cC[1] ^ wt[2]) \
           + __popc(cA[2] ^ wt[3]) + __popc(cB[2] ^ wt[4]) + __popc(cC[2] ^ wt[5]) \
           + __popc(cA[3] ^ wt[6]) + __popc(cB[3] ^ wt[7]) + __popc(cC[3] ^ wt[8]); \
    int d0 = Ci0 - 2 * a0, d1 = Ci1 - 2 * a1; \
    nb = sgn ? (max(d0, d1) >= T) : (min(d0, d1) <= T); \
} while (0)

    uint32_t A[4], B[4], C[4], D[4];
#pragma unroll
    for (int j = 0; j < 4; j++) { B[j] = tr[j * 28]; C[j] = tr[j * 28 + 1]; D[j] = tr[j * 28 + 2]; }

    bool nb0, nb1;
    {   // X = 0 edge: cols 0(B),1(C) with wt dx=1,2
        int a0 = __popc(B[0] ^ wt[1]) + __popc(C[0] ^ wt[2])
               + __popc(B[1] ^ wt[4]) + __popc(C[1] ^ wt[5])
               + __popc(B[2] ^ wt[7]) + __popc(C[2] ^ wt[8]);
        int a1 = __popc(B[1] ^ wt[1]) + __popc(C[1] ^ wt[2])
               + __popc(B[2] ^ wt[4]) + __popc(C[2] ^ wt[5])
               + __popc(B[3] ^ wt[7]) + __popc(C[3] ^ wt[8]);
        int d0 = Cl0 - 2 * a0, d1 = Cl1 - 2 * a1;
        nb0 = sgn ? (max(d0, d1) >= T) : (min(d0, d1) <= T);
    }
    TAPS2(B, C, D, nb1);
    uint32_t bal = __ballot_sync(0xffffffffu, nb0 | nb1);
    if (lane == 0) outp[0] = bal;

    for (int ox = 1; ox <= 12; ox++) {
#pragma unroll
        for (int j = 0; j < 4; j++) {
            A[j] = C[j]; B[j] = D[j];
            C[j] = tr[j * 28 + 2 * ox + 1];
            D[j] = tr[j * 28 + 2 * ox + 2];
        }
        TAPS2(A, B, C, nb0);
        TAPS2(B, C, D, nb1);
        bal = __ballot_sync(0xffffffffu, nb0 | nb1);
        if (lane == 0) outp[2 * ox] = bal;
    }

    // tail: X=26 (cols 25,26,27), X=27 edge (cols 26,27)
#pragma unroll
    for (int j = 0; j < 4; j++) { A[j] = C[j]; B[j] = D[j]; C[j] = tr[j * 28 + 27]; }
    TAPS2(A, B, C, nb0);
    {   // X = 27 edge: cols 26(B),27(C) with wt dx=0,1
        int a0 = __popc(B[0] ^ wt[0]) + __popc(C[0] ^ wt[1])
               + __popc(B[1] ^ wt[3]) + __popc(C[1] ^ wt[4])
               + __popc(B[2] ^ wt[6]) + __popc(C[2] ^ wt[7]);
        int a1 = __popc(B[1] ^ wt[0]) + __popc(C[1] ^ wt[1])
               + __popc(B[2] ^ wt[3]) + __popc(C[2] ^ wt[4])
               + __popc(B[3] ^ wt[6]) + __popc(C[3] ^ wt[7]);
        int d0 = Cr0 - 2 * a0, d1 = Cr1 - 2 * a1;
        nb1 = sgn ? (max(d0, d1) >= T) : (min(d0, d1) <= T);
    }
    bal = __ballot_sync(0xffffffffu, nb0 | nb1);
    if (lane == 0) outp[26] = bal;
#undef TAPS2
}

// ---------------- block2: warp/(img,row,half), sliding u64 register window ----------------
__global__ void __launch_bounds__(256) conv3_kernel() {
    __shared__ unsigned long long stile[4][4][14];     // 4 units x 4 input rows x 14 cols
    int tid = threadIdx.x;
    int U0 = blockIdx.x * 4;
    for (int i = tid; i < 224; i += 256) {
        int u = i / 56, r = i % 56, j = r / 14, col = r % 14;
        int U = U0 + u, b = U / 7, oy = U % 7;
        int ir = 2 * oy - 1 + j;
        stile[u][j][col] = (ir >= 0 && ir < 14) ? g_h2[b * 196 + ir * 14 + col] : 0ull;
    }
    __syncthreads();

    int w = tid >> 5, lane = tid & 31;
    int u = w >> 1, h = w & 1;
    int U = U0 + u, b = U / 7, oy = U % 7;
    int c = h * 32 + lane;

    unsigned long long wt[9];
#pragma unroll
    for (int t = 0; t < 9; t++) wt[t] = g_w3p[c * 10 + t];

    bool e0 = (oy == 0), e1 = (oy == 6);
    int v0 = e0 ? 2 : 3, v1 = e1 ? 2 : 3;
    int pw0 = __popcll(wt[0]), pw1 = __popcll(wt[1]), pw2 = __popcll(wt[2]);
    int pw6 = __popcll(wt[6]), pw7 = __popcll(wt[7]), pw8 = __popcll(wt[8]);
    int Ci0 = 192 * v0 + (e0 ? 2 * (pw0 + pw1 + pw2) : 0);
    int Ci1 = 192 * v1 + (e1 ? 2 * (pw6 + pw7 + pw8) : 0);
    int Cl0 = 128 * v0 + (e0 ? 2 * (pw1 + pw2) : 0);
    int Cl1 = 128 * v1 + (e1 ? 2 * (pw7 + pw8) : 0);
    int Cr0 = 128 * v0 + (e0 ? 2 * (pw0 + pw1) : 0);
    int Cr1 = 128 * v1 + (e1 ? 2 * (pw6 + pw7) : 0);

    int2 th = g_th3[c];
    int T = th.x;
    bool sgn = th.y != 0;
    const unsigned long long* tr = &stile[u][0][0];   // row stride 14
    uint32_t* outp = g_h3u + (b * 49 + oy * 7) * 2 + h;

#define TAPS3(cA, cB, cC, nb) do { \
    int a0 = __popcll(cA[0] ^ wt[0]) + __popcll(cB[0] ^ wt[1]) + __popcll(cC[0] ^ wt[2]) \
           + __popcll(cA[1] ^ wt[3]) + __popcll(cB[1] ^ wt[4]) + __popcll(cC[1] ^ wt[5]) \
           + __popcll(cA[2] ^ wt[6]) + __popcll(cB[2] ^ wt[7]) + __popcll(cC[2] ^ wt[8]); \
    int a1 = __popcll(cA[1] ^ wt[0]) + __popcll(cB[1] ^ wt[1]) + __popcll(cC[1] ^ wt[2]) \
           + __popcll(cA[2] ^ wt[3]) + __popcll(cB[2] ^ wt[4]) + __popcll(cC[2] ^ wt[5]) \
           + __popcll(cA[3] ^ wt[6]) + __popcll(cB[3] ^ wt[7]) + __popcll(cC[3] ^ wt[8]); \
    int d0 = Ci0 - 2 * a0, d1 = Ci1 - 2 * a1; \
    nb = sgn ? (max(d0, d1) >= T) : (min(d0, d1) <= T); \
} while (0)

    unsigned long long A[4], B[4], C[4];
#pragma unroll
    for (int j = 0; j < 4; j++) { B[j] = tr[j * 14]; C[j] = tr[j * 14 + 1]; }

    bool nb0, nb1;
    {   // X = 0 edge: cols 0(B),1(C) with wt dx=1,2
        int a0 = __popcll(B[0] ^ wt[1]) + __popcll(C[0] ^ wt[2])
               + __popcll(B[1] ^ wt[4]) + __popcll(C[1] ^ wt[5])
               + __popcll(B[2] ^ wt[7]) + __popcll(C[2] ^ wt[8]);
        int a1 = __popcll(B[1] ^ wt[1]) + __popcll(C[1] ^ wt[2])
               + __popcll(B[2] ^ wt[4]) + __popcll(C[2] ^ wt[5])
               + __popcll(B[3] ^ wt[7]) + __popcll(C[3] ^ wt[8]);
        int d0 = Cl0 - 2 * a0, d1 = Cl1 - 2 * a1;
        nb0 = sgn ? (max(d0, d1) >= T) : (min(d0, d1) <= T);
    }
    // X = 1
#pragma unroll
    for (int j = 0; j < 4; j++) { A[j] = B[j]; B[j] = C[j]; C[j] = tr[j * 14 + 2]; }
    TAPS3(A, B, C, nb1);
    uint32_t bal = __ballot_sync(0xffffffffu, nb0 | nb1);
    if (lane == 0) outp[0] = bal;

    for (int ox = 1; ox <= 5; ox++) {
#pragma unroll
        for (int j = 0; j < 4; j++) { A[j] = B[j]; B[j] = C[j]; C[j] = tr[j * 14 + 2 * ox + 1]; }
        TAPS3(A, B, C, nb0);
#pragma unroll
        for (int j = 0; j < 4; j++) { A[j] = B[j]; B[j] = C[j]; C[j] = tr[j * 14 + 2 * ox + 2]; }
        TAPS3(A, B, C, nb1);
        bal = __ballot_sync(0xffffffffu, nb0 | nb1);
        if (lane == 0) outp[2 * ox] = bal;
    }

    // X = 12, then X = 13 edge
#pragma unroll
    for (int j = 0; j < 4; j++) { A[j] = B[j]; B[j] = C[j]; C[j] = tr[j * 14 + 13]; }
    TAPS3(A, B, C, nb0);
    {   // X = 13 edge: cols 12(B),13(C) with wt dx=0,1
        int a0 = __popcll(B[0] ^ wt[0]) + __popcll(C[0] ^ wt[1])
               + __popcll(B[1] ^ wt[3]) + __popcll(C[1] ^ wt[4])
               + __popcll(B[2] ^ wt[6]) + __popcll(C[2] ^ wt[7]);
        int a1 = __popcll(B[1] ^ wt[0]) + __popcll(C[1] ^ wt[1])
               + __popcll(B[2] ^ wt[3]) + __popcll(C[2] ^ wt[4])
               + __popcll(B[3] ^ wt[6]) + __popcll(C[3] ^ wt[7]);
        int d0 = Cr0 - 2 * a0, d1 = Cr1 - 2 * a1;
        nb1 = sgn ? (max(d0, d1) >= T) : (min(d0, d1) <= T);
    }
    bal = __ballot_sync(0xffffffffu, nb0 | nb1);
    if (lane == 0) outp[12] = bal;
#undef TAPS3
}

// ---------------- classifier ----------------
__global__ void __launch_bounds__(256) fc_kernel(const float* __restrict__ w_head,
                                                 const float* __restrict__ b_head,
                                                 float* __restrict__ out) {
    __shared__ unsigned long long xrow[49];
    __shared__ float h4[256];
    int b = blockIdx.x, t = threadIdx.x;
    if (t < 49) {
        uint32_t lo = g_h3u[(b * 49 + t) * 2];
        uint32_t hi = g_h3u[(b * 49 + t) * 2 + 1];
        xrow[t] = (unsigned long long)lo | ((unsigned long long)hi << 32);
    }
    __syncthreads();

    const unsigned long long* wr = g_wfcp + t * 49;
    int acc = 0;
#pragma unroll
    for (int p = 0; p < 49; p++) acc += __popcll(xrow[p] ^ wr[p]);
    float4 bn = g_bn4[t];
    h4[t] = ((float)(3136 - 2 * acc) - bn.y) * bn.x + bn.z;
    __syncthreads();

    if (t < 10) {
        float s = b_head[t];
        const float* wh = w_head + t * 256;
#pragma unroll 8
        for (int c = 0; c < 256; c++) s += h4[c] * wh[c];
        out[b * 10 + t] = s;
    }
}

// ---------------- launch ----------------
extern "C" void kernel_launch(void* const* d_in, const int* in_sizes, int n_in,
                              void* d_out, int out_size) {
    const float* x      = (const float*)d_in[0];
    const float* w_stem = (const float*)d_in[1];
    const float* g1 = (const float*)d_in[2];
    const float* b1 = (const float*)d_in[3];
    const float* m1 = (const float*)d_in[4];
    const float* v1 = (const float*)d_in[5];
    const float* w2 = (const float*)d_in[6];
    const float* g2 = (const float*)d_in[7];
    const float* b2 = (const float*)d_in[8];
    const float* m2 = (const float*)d_in[9];
    const float* v2 = (const float*)d_in[10];
    const float* w3 = (const float*)d_in[11];
    const float* g3 = (const float*)d_in[12];
    const float* b3 = (const float*)d_in[13];
    const float* m3 = (const float*)d_in[14];
    const float* v3 = (const float*)d_in[15];
    const float* w_fc = (const float*)d_in[16];
    const float* g4 = (const float*)d_in[17];
    const float* b4 = (const float*)d_in[18];
    const float* m4 = (const float*)d_in[19];
    const float* v4 = (const float*)d_in[20];
    const float* w_head = (const float*)d_in[21];
    const float* b_head = (const float*)d_in[22];
    float* out = (float*)d_out;

    pack_kernel<<<57, 256>>>(w2, w3, w_fc, g1, v1, m1, b1, g2, v2, m2, b2,
                             g3, v3, m3, b3, g4, v4, m4, b4);
    stem_kernel<<<(BATCH * 784 * 2) / 256, 256>>>(x, w_stem);
    conv2_kernel<<<(BATCH * 14) / 4, 256>>>();   // 7168 blocks
    conv3_kernel<<<(BATCH * 7) / 4, 256>>>();    // 3584 blocks
    fc_kernel<<<BATCH, 256>>>(w_head, b_head, out);
}

// round 10
// speedup vs baseline: 1.6217x; 1.6217x over previous
#include <cuda_runtime.h>
#include <stdint.h>

#define BATCH 2048
#define EPS 1e-5f

// ---------------- static scratch ----------------
__device__ uint32_t           g_h1[BATCH * 784];        // stem out, 32 ch packed
__device__ unsigned long long g_h2[BATCH * 196];        // block1 out, 64 ch packed (u32 halves)
__device__ uint32_t           g_h3u[BATCH * 49 * 2];    // block2 out, u32 halves
__device__ uint32_t           g_w2p[64 * 12];           // sign(w2), [ch][tap] stride 12
__device__ unsigned long long g_w3p[64 * 10];           // sign(w3), [ch][tap] stride 10
__device__ unsigned long long g_wfcp[256 * 49];         // sign(w_fc)
__device__ float4 g_bn1[32], g_bn4[256];                // (inv, mean, beta, 0)
__device__ int2   g_th2[64], g_th3[64];                 // (integer threshold, sgn)

// ---------------- packing + BN + integer thresholds ----------------
__global__ void pack_kernel(const float* __restrict__ w2, const float* __restrict__ w3,
                            const float* __restrict__ wfc,
                            const float* __restrict__ g1, const float* __restrict__ v1,
                            const float* __restrict__ m1, const float* __restrict__ b1,
                            const float* __restrict__ g2, const float* __restrict__ v2,
                            const float* __restrict__ m2, const float* __restrict__ b2,
                            const float* __restrict__ g3, const float* __restrict__ v3,
                            const float* __restrict__ m3, const float* __restrict__ b3,
                            const float* __restrict__ g4, const float* __restrict__ v4,
                            const float* __restrict__ m4, const float* __restrict__ b4) {
    int idx = blockIdx.x * 256 + threadIdx.x;
    if (idx < 768) {                                   // w2: [64,32,3,3] -> stride 12
        int o = idx / 12, t = idx % 12;
        uint32_t bits = 0;
        if (t < 9)
            for (int c = 0; c < 32; c++)
                bits |= (w2[o * 288 + c * 9 + t] >= 0.f ? 1u : 0u) << c;
        g_w2p[idx] = bits;
    } else if (idx < 1408) {                           // w3: [64,64,3,3] -> stride 10
        int j = idx - 768; int o = j / 10, t = j % 10;
        unsigned long long bits = 0;
        if (t < 9)
            for (int c = 0; c < 64; c++)
                bits |= (unsigned long long)(w3[o * 576 + c * 9 + t] >= 0.f) << c;
        g_w3p[j] = bits;
    } else if (idx < 13952) {                          // w_fc: [256,3136]
        int j = idx - 1408; int o = j / 49, p = j % 49;
        unsigned long long bits = 0;
        for (int c = 0; c < 64; c++)
            bits |= (unsigned long long)(wfc[o * 3136 + c * 49 + p] >= 0.f) << c;
        g_wfcp[j] = bits;
    } else if (idx < 13984) {
        int c = idx - 13952;
        g_bn1[c] = make_float4(g1[c] / sqrtf(v1[c] + EPS), m1[c], b1[c], 0.f);
    } else if (idx < 14240) {
        int c = idx - 13984;
        g_bn4[c] = make_float4(g4[c] / sqrtf(v4[c] + EPS), m4[c], b4[c], 0.f);
    } else if (idx < 14304) {                          // conv2 thresholds (d in [-288,288], even)
        int c = idx - 14240;
        float inv = g2[c] / sqrtf(v2[c] + EPS), m = m2[c], be = b2[c];
        int sgn = (inv >= 0.f) ? 1 : 0;
        int T;
        if (sgn) {
            T = 10000;
            for (int d = -288; d <= 288; d += 2)
                if (((float)d - m) * inv + be >= 0.f) { T = d; break; }
        } else {
            T = -10000;
            for (int d = 288; d >= -288; d -= 2)
                if (((float)d - m) * inv + be >= 0.f) { T = d; break; }
        }
        g_th2[c] = make_int2(T, sgn);
    } else if (idx < 14368) {                          // conv3 thresholds (d in [-576,576], even)
        int c = idx - 14304;
        float inv = g3[c] / sqrtf(v3[c] + EPS), m = m3[c], be = b3[c];
        int sgn = (inv >= 0.f) ? 1 : 0;
        int T;
        if (sgn) {
            T = 10000;
            for (int d = -576; d <= 576; d += 2)
                if (((float)d - m) * inv + be >= 0.f) { T = d; break; }
        } else {
            T = -10000;
            for (int d = 576; d >= -576; d -= 2)
                if (((float)d - m) * inv + be >= 0.f) { T = d; break; }
        }
        g_th3[c] = make_int2(T, sgn);
    }
}

// ---------------- stem: fp32 conv3x3(1->32) + BN + sign, 16 ch/thread ----------------
__global__ void __launch_bounds__(256) stem_kernel(const float* __restrict__ x,
                                                   const float* __restrict__ ws) {
    __shared__ float sw[288];
    __shared__ float4 sbn[32];
    int t = threadIdx.x;
    for (int i = t; i < 288; i += 256) sw[i] = ws[i];
    if (t < 32) sbn[t] = g_bn1[t];
    __syncthreads();

    int idx = blockIdx.x * 256 + t;
    int pix = idx >> 1, half = idx & 1;
    int b = pix / 784, p = pix % 784;
    int y = p / 28, xx = p % 28;
    const float* xb = x + b * 784;

    float win[9];
#pragma unroll
    for (int dy = 0; dy < 3; dy++)
#pragma unroll
        for (int dx = 0; dx < 3; dx++) {
            int yy = y + dy - 1, xc = xx + dx - 1;
            win[dy * 3 + dx] = (yy >= 0 && yy < 28 && xc >= 0 && xc < 28) ? xb[yy * 28 + xc] : 0.f;
        }

    int cb = half * 16;
    uint32_t bits = 0;
#pragma unroll
    for (int ci = 0; ci < 16; ci++) {
        int c = cb + ci;
        float s = 0.f;
#pragma unroll
        for (int k = 0; k < 9; k++) s += sw[c * 9 + k] * win[k];
        float4 bn = sbn[c];
        float v = (s - bn.y) * bn.x + bn.z;
        bits |= (v >= 0.f ? 1u : 0u) << ci;
    }
    ((uint16_t*)g_h1)[pix * 2 + half] = (uint16_t)bits;
}

// ---------------- block1: warp/(img,row,half,colgroup), lane = channel ----------------
__global__ void __launch_bounds__(256) conv2_kernel() {
    __shared__ uint32_t stile[2][4][28];               // 2 units x 4 input rows x 28 cols
    int tid = threadIdx.x;
    int U0 = blockIdx.x * 2;
    for (int i = tid; i < 224; i += 256) {
        int u = i / 112, r = i % 112, j = r / 28, col = r % 28;
        int U = U0 + u, b = U / 14, oy = U % 14;
        int ir = 2 * oy - 1 + j;
        stile[u][j][col] = (ir >= 0 && ir < 28) ? g_h1[b * 784 + ir * 28 + col] : 0u;
    }
    __syncthreads();

    int w = tid >> 5, lane = tid & 31;
    int u = w >> 2, h = w & 1, cg = (w >> 1) & 1;
    int U = U0 + u, b = U / 14, oy = U % 14;
    int c = h * 32 + lane;

    uint32_t wt[9];
#pragma unroll
    for (int t = 0; t < 9; t++) wt[t] = g_w2p[c * 12 + t];

    bool e0 = (oy == 0), e1 = (oy == 13);
    int v0 = e0 ? 2 : 3, v1 = e1 ? 2 : 3;
    int pw0 = __popc(wt[0]), pw1 = __popc(wt[1]), pw2 = __popc(wt[2]);
    int pw6 = __popc(wt[6]), pw7 = __popc(wt[7]), pw8 = __popc(wt[8]);
    int Ci0 = 96 * v0 + (e0 ? 2 * (pw0 + pw1 + pw2) : 0);
    int Ci1 = 96 * v1 + (e1 ? 2 * (pw6 + pw7 + pw8) : 0);

    int2 th = g_th2[c];
    int T = th.x;
    bool sgn = th.y != 0;
    const uint32_t* tr = &stile[u][0][0];
    uint32_t* outp = ((uint32_t*)g_h2) + (b * 196 + oy * 14) * 2 + h;

#define C2_INT(X, nb) { \
    int a0 = 0, a1 = 0; \
    _Pragma("unroll") \
    for (int dy = 0; dy < 3; dy++) { \
        a0 += __popc(tr[dy*28+(X)-1] ^ wt[3*dy]) + __popc(tr[dy*28+(X)] ^ wt[3*dy+1]) \
            + __popc(tr[dy*28+(X)+1] ^ wt[3*dy+2]); \
        a1 += __popc(tr[(dy+1)*28+(X)-1] ^ wt[3*dy]) + __popc(tr[(dy+1)*28+(X)] ^ wt[3*dy+1]) \
            + __popc(tr[(dy+1)*28+(X)+1] ^ wt[3*dy+2]); \
    } \
    int d0 = Ci0 - 2 * a0, d1 = Ci1 - 2 * a1; \
    nb = sgn ? (max(d0, d1) >= T) : (min(d0, d1) <= T); }

    bool nb0, nb1;
    uint32_t bal;
    if (cg == 0) {
        // output cols 0..6 (pre-pool X 0..13); X=0 is left edge
        int Cl0 = 64 * v0 + (e0 ? 2 * (pw1 + pw2) : 0);
        int Cl1 = 64 * v1 + (e1 ? 2 * (pw7 + pw8) : 0);
        {   // X = 0 edge: taps dx in {1,2} read cols 0,1
            int a0 = __popc(tr[0] ^ wt[1]) + __popc(tr[1] ^ wt[2])
                   + __popc(tr[28] ^ wt[4]) + __popc(tr[29] ^ wt[5])
                   + __popc(tr[56] ^ wt[7]) + __popc(tr[57] ^ wt[8]);
            int a1 = __popc(tr[28] ^ wt[1]) + __popc(tr[29] ^ wt[2])
                   + __popc(tr[56] ^ wt[4]) + __popc(tr[57] ^ wt[5])
                   + __popc(tr[84] ^ wt[7]) + __popc(tr[85] ^ wt[8]);
            int d0 = Cl0 - 2 * a0, d1 = Cl1 - 2 * a1;
            nb0 = sgn ? (max(d0, d1) >= T) : (min(d0, d1) <= T);
        }
        C2_INT(1, nb1);
        bal = __ballot_sync(0xffffffffu, nb0 | nb1);
        if (lane == 0) outp[0] = bal;
#pragma unroll 2
        for (int ox = 1; ox <= 6; ox++) {
            C2_INT(2 * ox, nb0);
            C2_INT(2 * ox + 1, nb1);
            bal = __ballot_sync(0xffffffffu, nb0 | nb1);
            if (lane == 0) outp[2 * ox] = bal;
        }
    } else {
        // output cols 7..13 (pre-pool X 14..27); X=27 is right edge
        int Cr0 = 64 * v0 + (e0 ? 2 * (pw0 + pw1) : 0);
        int Cr1 = 64 * v1 + (e1 ? 2 * (pw6 + pw7) : 0);
#pragma unroll 2
        for (int ox = 7; ox <= 12; ox++) {
            C2_INT(2 * ox, nb0);
            C2_INT(2 * ox + 1, nb1);
            bal = __ballot_sync(0xffffffffu, nb0 | nb1);
            if (lane == 0) outp[2 * ox] = bal;
        }
        C2_INT(26, nb0);
        {   // X = 27 edge: taps dx in {0,1} read cols 26,27
            int a0 = __popc(tr[26] ^ wt[0]) + __popc(tr[27] ^ wt[1])
                   + __popc(tr[54] ^ wt[3]) + __popc(tr[55] ^ wt[4])
                   + __popc(tr[82] ^ wt[6]) + __popc(tr[83] ^ wt[7]);
            int a1 = __popc(tr[54] ^ wt[0]) + __popc(tr[55] ^ wt[1])
                   + __popc(tr[82] ^ wt[3]) + __popc(tr[83] ^ wt[4])
                   + __popc(tr[110] ^ wt[6]) + __popc(tr[111] ^ wt[7]);
            int d0 = Cr0 - 2 * a0, d1 = Cr1 - 2 * a1;
            nb1 = sgn ? (max(d0, d1) >= T) : (min(d0, d1) <= T);
        }
        bal = __ballot_sync(0xffffffffu, nb0 | nb1);
        if (lane == 0) outp[26] = bal;
    }
#undef C2_INT
}

// ---------------- block2: warp/(img,row,half,colgroup), lane = channel ----------------
__global__ void __launch_bounds__(256) conv3_kernel() {
    __shared__ unsigned long long stile[2][4][14];     // 2 units x 4 input rows x 14 cols
    int tid = threadIdx.x;
    int U0 = blockIdx.x * 2;
    for (int i = tid; i < 112; i += 256) {
        int u = i / 56, r = i % 56, j = r / 14, col = r % 14;
        int U = U0 + u, b = U / 7, oy = U % 7;
        int ir = 2 * oy - 1 + j;
        stile[u][j][col] = (ir >= 0 && ir < 14) ? g_h2[b * 196 + ir * 14 + col] : 0ull;
    }
    __syncthreads();

    int w = tid >> 5, lane = tid & 31;
    int u = w >> 2, h = w & 1, cg = (w >> 1) & 1;
    int U = U0 + u, b = U / 7, oy = U % 7;
    int c = h * 32 + lane;

    unsigned long long wt[9];
#pragma unroll
    for (int t = 0; t < 9; t++) wt[t] = g_w3p[c * 10 + t];

    bool e0 = (oy == 0), e1 = (oy == 6);
    int v0 = e0 ? 2 : 3, v1 = e1 ? 2 : 3;
    int pw0 = __popcll(wt[0]), pw1 = __popcll(wt[1]), pw2 = __popcll(wt[2]);
    int pw6 = __popcll(wt[6]), pw7 = __popcll(wt[7]), pw8 = __popcll(wt[8]);
    int Ci0 = 192 * v0 + (e0 ? 2 * (pw0 + pw1 + pw2) : 0);
    int Ci1 = 192 * v1 + (e1 ? 2 * (pw6 + pw7 + pw8) : 0);

    int2 th = g_th3[c];
    int T = th.x;
    bool sgn = th.y != 0;
    const unsigned long long* tr = &stile[u][0][0];   // row stride 14
    uint32_t* outp = g_h3u + (b * 49 + oy * 7) * 2 + h;

#define C3_INT(X, nb) { \
    int a0 = 0, a1 = 0; \
    _Pragma("unroll") \
    for (int dy = 0; dy < 3; dy++) { \
        a0 += __popcll(tr[dy*14+(X)-1] ^ wt[3*dy]) + __popcll(tr[dy*14+(X)] ^ wt[3*dy+1]) \
            + __popcll(tr[dy*14+(X)+1] ^ wt[3*dy+2]); \
        a1 += __popcll(tr[(dy+1)*14+(X)-1] ^ wt[3*dy]) + __popcll(tr[(dy+1)*14+(X)] ^ wt[3*dy+1]) \
            + __popcll(tr[(dy+1)*14+(X)+1] ^ wt[3*dy+2]); \
    } \
    int d0 = Ci0 - 2 * a0, d1 = Ci1 - 2 * a1; \
    nb = sgn ? (max(d0, d1) >= T) : (min(d0, d1) <= T); }

    bool nb0, nb1;
    uint32_t bal;
    if (cg == 0) {
        // output cols 0..3 (pre-pool X 0..7); X=0 is left edge
        int Cl0 = 128 * v0 + (e0 ? 2 * (pw1 + pw2) : 0);
        int Cl1 = 128 * v1 + (e1 ? 2 * (pw7 + pw8) : 0);
        {   // X = 0 edge
            int a0 = __popcll(tr[0] ^ wt[1]) + __popcll(tr[1] ^ wt[2])
                   + __popcll(tr[14] ^ wt[4]) + __popcll(tr[15] ^ wt[5])
                   + __popcll(tr[28] ^ wt[7]) + __popcll(tr[29] ^ wt[8]);
            int a1 = __popcll(tr[14] ^ wt[1]) + __popcll(tr[15] ^ wt[2])
                   + __popcll(tr[28] ^ wt[4]) + __popcll(tr[29] ^ wt[5])
                   + __popcll(tr[42] ^ wt[7]) + __popcll(tr[43] ^ wt[8]);
            int d0 = Cl0 - 2 * a0, d1 = Cl1 - 2 * a1;
            nb0 = sgn ? (max(d0, d1) >= T) : (min(d0, d1) <= T);
        }
        C3_INT(1, nb1);
        bal = __ballot_sync(0xffffffffu, nb0 | nb1);
        if (lane == 0) outp[0] = bal;
#pragma unroll
        for (int ox = 1; ox <= 3; ox++) {
            C3_INT(2 * ox, nb0);
            C3_INT(2 * ox + 1, nb1);
            bal = __ballot_sync(0xffffffffu, nb0 | nb1);
            if (lane == 0) outp[2 * ox] = bal;
        }
    } else {
        // output cols 4..6 (pre-pool X 8..13); X=13 is right edge
        int Cr0 = 128 * v0 + (e0 ? 2 * (pw0 + pw1) : 0);
        int Cr1 = 128 * v1 + (e1 ? 2 * (pw6 + pw7) : 0);
#pragma unroll
        for (int ox = 4; ox <= 5; ox++) {
            C3_INT(2 * ox, nb0);
            C3_INT(2 * ox + 1, nb1);
            bal = __ballot_sync(0xffffffffu, nb0 | nb1);
            if (lane == 0) outp[2 * ox] = bal;
        }
        C3_INT(12, nb0);
        {   // X = 13 edge
            int a0 = __popcll(tr[12] ^ wt[0]) + __popcll(tr[13] ^ wt[1])
                   + __popcll(tr[26] ^ wt[3]) + __popcll(tr[27] ^ wt[4])
                   + __popcll(tr[40] ^ wt[6]) + __popcll(tr[41] ^ wt[7]);
            int a1 = __popcll(tr[26] ^ wt[0]) + __popcll(tr[27] ^ wt[1])
                   + __popcll(tr[40] ^ wt[3]) + __popcll(tr[41] ^ wt[4])
                   + __popcll(tr[54] ^ wt[6]) + __popcll(tr[55] ^ wt[7]);
            int d0 = Cr0 - 2 * a0, d1 = Cr1 - 2 * a1;
            nb1 = sgn ? (max(d0, d1) >= T) : (min(d0, d1) <= T);
        }
        bal = __ballot_sync(0xffffffffu, nb0 | nb1);
        if (lane == 0) outp[12] = bal;
    }
#undef C3_INT
}

// ---------------- classifier ----------------
__global__ void __launch_bounds__(256) fc_kernel(const float* __restrict__ w_head,
                                                 const float* __restrict__ b_head,
                                                 float* __restrict__ out) {
    __shared__ unsigned long long xrow[49];
    __shared__ float h4[256];
    int b = blockIdx.x, t = threadIdx.x;
    if (t < 49) {
        uint32_t lo = g_h3u[(b * 49 + t) * 2];
        uint32_t hi = g_h3u[(b * 49 + t) * 2 + 1];
        xrow[t] = (unsigned long long)lo | ((unsigned long long)hi << 32);
    }
    __syncthreads();

    const unsigned long long* wr = g_wfcp + t * 49;
    int acc = 0;
#pragma unroll
    for (int p = 0; p < 49; p++) acc += __popcll(xrow[p] ^ wr[p]);
    float4 bn = g_bn4[t];
    h4[t] = ((float)(3136 - 2 * acc) - bn.y) * bn.x + bn.z;
    __syncthreads();

    if (t < 10) {
        float s = b_head[t];
        const float* wh = w_head + t * 256;
#pragma unroll 8
        for (int c = 0; c < 256; c++) s += h4[c] * wh[c];
        out[b * 10 + t] = s;
    }
}

// ---------------- launch ----------------
extern "C" void kernel_launch(void* const* d_in, const int* in_sizes, int n_in,
                              void* d_out, int out_size) {
    const float* x      = (const float*)d_in[0];
    const float* w_stem = (const float*)d_in[1];
    const float* g1 = (const float*)d_in[2];
    const float* b1 = (const float*)d_in[3];
    const float* m1 = (const float*)d_in[4];
    const float* v1 = (const float*)d_in[5];
    const float* w2 = (const float*)d_in[6];
    const float* g2 = (const float*)d_in[7];
    const float* b2 = (const float*)d_in[8];
    const float* m2 = (const float*)d_in[9];
    const float* v2 = (const float*)d_in[10];
    const float* w3 = (const float*)d_in[11];
    const float* g3 = (const float*)d_in[12];
    const float* b3 = (const float*)d_in[13];
    const float* m3 = (const float*)d_in[14];
    const float* v3 = (const float*)d_in[15];
    const float* w_fc = (const float*)d_in[16];
    const float* g4 = (const float*)d_in[17];
    const float* b4 = (const float*)d_in[18];
    const float* m4 = (const float*)d_in[19];
    const float* v4 = (const float*)d_in[20];
    const float* w_head = (const float*)d_in[21];
    const float* b_head = (const float*)d_in[22];
    float* out = (float*)d_out;

    pack_kernel<<<57, 256>>>(w2, w3, w_fc, g1, v1, m1, b1, g2, v2, m2, b2,
                             g3, v3, m3, b3, g4, v4, m4, b4);
    stem_kernel<<<(BATCH * 784 * 2) / 256, 256>>>(x, w_stem);
    conv2_kernel<<<(BATCH * 14) / 2, 256>>>();   // 14336 blocks: 2 units x (2 halves x 2 colgroups)
    conv3_kernel<<<(BATCH * 7) / 2, 256>>>();    // 7168 blocks
    fc_kernel<<<BATCH, 256>>>(w_head, b_head, out);
}

// round 11
// speedup vs baseline: 1.7970x; 1.1081x over previous
#include <cuda_runtime.h>
#include <stdint.h>

#define BATCH 2048
#define EPS 1e-5f

// ---------------- static scratch ----------------
__device__ uint32_t           g_h1[BATCH * 784];        // stem out, 32 ch packed
__device__ unsigned long long g_h2[BATCH * 196];        // block1 out, 64 ch packed (u32 halves)
__device__ uint32_t           g_h3u[BATCH * 49 * 2];    // block2 out, u32 halves
__device__ uint32_t           g_w2p[64 * 12];           // sign(w2), [ch][tap] stride 12
__device__ unsigned long long g_w3p[64 * 10];           // sign(w3), [ch][tap] stride 10
__device__ unsigned long long g_wfcp[256 * 49];         // sign(w_fc)
__device__ float4 g_bn1[32], g_bn4[256];                // (inv, mean, beta, 0)
__device__ int2   g_th2[64], g_th3[64];                 // (integer threshold, sgn)

// carry-save adder compressors (single LOP3 each after ptxas fusion)
#define CSA32(s, c, x, y, z) do { uint32_t _x = (x), _y = (y), _z = (z); \
    (s) = _x ^ _y ^ _z; (c) = (_x & _y) | (_z & (_x | _y)); } while (0)
#define CSA64(s, c, x, y, z) do { unsigned long long _x = (x), _y = (y), _z = (z); \
    (s) = _x ^ _y ^ _z; (c) = (_x & _y) | (_z & (_x | _y)); } while (0)

// popcount of sum of 9 words via full CSA tree: 4 POPC instead of 9
#define POP9_32(res, v0, v1, v2, v3, v4, v5, v6, v7, v8) do { \
    uint32_t _s1, _c1, _s2, _c2, _s3, _c3, _s4, _c4, _s5, _c5; \
    CSA32(_s1, _c1, v0, v1, v2); CSA32(_s2, _c2, v3, v4, v5); CSA32(_s3, _c3, v6, v7, v8); \
    CSA32(_s4, _c4, _s1, _s2, _s3); CSA32(_s5, _c5, _c1, _c2, _c3); \
    (res) = __popc(_s4) + 2 * (__popc(_c4) + __popc(_s5)) + 4 * __popc(_c5); } while (0)
#define POP9_64(res, v0, v1, v2, v3, v4, v5, v6, v7, v8) do { \
    unsigned long long _s1, _c1, _s2, _c2, _s3, _c3, _s4, _c4, _s5, _c5; \
    CSA64(_s1, _c1, v0, v1, v2); CSA64(_s2, _c2, v3, v4, v5); CSA64(_s3, _c3, v6, v7, v8); \
    CSA64(_s4, _c4, _s1, _s2, _s3); CSA64(_s5, _c5, _c1, _c2, _c3); \
    (res) = __popcll(_s4) + 2 * (__popcll(_c4) + __popcll(_s5)) + 4 * __popcll(_c5); } while (0)

// ---------------- packing + BN + integer thresholds ----------------
__global__ void pack_kernel(const float* __restrict__ w2, const float* __restrict__ w3,
                            const float* __restrict__ wfc,
                            const float* __restrict__ g1, const float* __restrict__ v1,
                            const float* __restrict__ m1, const float* __restrict__ b1,
                            const float* __restrict__ g2, const float* __restrict__ v2,
                            const float* __restrict__ m2, const float* __restrict__ b2,
                            const float* __restrict__ g3, const float* __restrict__ v3,
                            const float* __restrict__ m3, const float* __restrict__ b3,
                            const float* __restrict__ g4, const float* __restrict__ v4,
                            const float* __restrict__ m4, const float* __restrict__ b4) {
    int idx = blockIdx.x * 256 + threadIdx.x;
    if (idx < 768) {                                   // w2: [64,32,3,3] -> stride 12
        int o = idx / 12, t = idx % 12;
        uint32_t bits = 0;
        if (t < 9)
            for (int c = 0; c < 32; c++)
                bits |= (w2[o * 288 + c * 9 + t] >= 0.f ? 1u : 0u) << c;
        g_w2p[idx] = bits;
    } else if (idx < 1408) {                           // w3: [64,64,3,3] -> stride 10
        int j = idx - 768; int o = j / 10, t = j % 10;
        unsigned long long bits = 0;
        if (t < 9)
            for (int c = 0; c < 64; c++)
                bits |= (unsigned long long)(w3[o * 576 + c * 9 + t] >= 0.f) << c;
        g_w3p[j] = bits;
    } else if (idx < 13952) {                          // w_fc: [256,3136]
        int j = idx - 1408; int o = j / 49, p = j % 49;
        unsigned long long bits = 0;
        for (int c = 0; c < 64; c++)
            bits |= (unsigned long long)(wfc[o * 3136 + c * 49 + p] >= 0.f) << c;
        g_wfcp[j] = bits;
    } else if (idx < 13984) {
        int c = idx - 13952;
        g_bn1[c] = make_float4(g1[c] / sqrtf(v1[c] + EPS), m1[c], b1[c], 0.f);
    } else if (idx < 14240) {
        int c = idx - 13984;
        g_bn4[c] = make_float4(g4[c] / sqrtf(v4[c] + EPS), m4[c], b4[c], 0.f);
    } else if (idx < 14304) {                          // conv2 thresholds (d in [-288,288], even)
        int c = idx - 14240;
        float inv = g2[c] / sqrtf(v2[c] + EPS), m = m2[c], be = b2[c];
        int sgn = (inv >= 0.f) ? 1 : 0;
        int T;
        if (sgn) {
            T = 10000;
            for (int d = -288; d <= 288; d += 2)
                if (((float)d - m) * inv + be >= 0.f) { T = d; break; }
        } else {
            T = -10000;
            for (int d = 288; d >= -288; d -= 2)
                if (((float)d - m) * inv + be >= 0.f) { T = d; break; }
        }
        g_th2[c] = make_int2(T, sgn);
    } else if (idx < 14368) {                          // conv3 thresholds (d in [-576,576], even)
        int c = idx - 14304;
        float inv = g3[c] / sqrtf(v3[c] + EPS), m = m3[c], be = b3[c];
        int sgn = (inv >= 0.f) ? 1 : 0;
        int T;
        if (sgn) {
            T = 10000;
            for (int d = -576; d <= 576; d += 2)
                if (((float)d - m) * inv + be >= 0.f) { T = d; break; }
        } else {
            T = -10000;
            for (int d = 576; d >= -576; d -= 2)
                if (((float)d - m) * inv + be >= 0.f) { T = d; break; }
        }
        g_th3[c] = make_int2(T, sgn);
    }
}

// ---------------- stem: fp32 conv3x3(1->32) + BN + sign, 16 ch/thread ----------------
__global__ void __launch_bounds__(256) stem_kernel(const float* __restrict__ x,
                                                   const float* __restrict__ ws) {
    __shared__ float sw[288];
    __shared__ float4 sbn[32];
    int t = threadIdx.x;
    for (int i = t; i < 288; i += 256) sw[i] = ws[i];
    if (t < 32) sbn[t] = g_bn1[t];
    __syncthreads();

    int idx = blockIdx.x * 256 + t;
    int pix = idx >> 1, half = idx & 1;
    int b = pix / 784, p = pix % 784;
    int y = p / 28, xx = p % 28;
    const float* xb = x + b * 784;

    float win[9];
#pragma unroll
    for (int dy = 0; dy < 3; dy++)
#pragma unroll
        for (int dx = 0; dx < 3; dx++) {
            int yy = y + dy - 1, xc = xx + dx - 1;
            win[dy * 3 + dx] = (yy >= 0 && yy < 28 && xc >= 0 && xc < 28) ? xb[yy * 28 + xc] : 0.f;
        }

    int cb = half * 16;
    uint32_t bits = 0;
#pragma unroll
    for (int ci = 0; ci < 16; ci++) {
        int c = cb + ci;
        float s = 0.f;
#pragma unroll
        for (int k = 0; k < 9; k++) s += sw[c * 9 + k] * win[k];
        float4 bn = sbn[c];
        float v = (s - bn.y) * bn.x + bn.z;
        bits |= (v >= 0.f ? 1u : 0u) << ci;
    }
    ((uint16_t*)g_h1)[pix * 2 + half] = (uint16_t)bits;
}

// ---------------- block1: warp/(img,row,half), lane = channel, CSA popc ----------------
__global__ void __launch_bounds__(256) conv2_kernel() {
    __shared__ uint32_t stile[4][4][28];               // 4 units x 4 input rows x 28 cols
    int tid = threadIdx.x;
    int U0 = blockIdx.x * 4;
    for (int i = tid; i < 448; i += 256) {
        int u = i / 112, r = i % 112, j = r / 28, col = r % 28;
        int U = U0 + u, b = U / 14, oy = U % 14;
        int ir = 2 * oy - 1 + j;
        stile[u][j][col] = (ir >= 0 && ir < 28) ? g_h1[b * 784 + ir * 28 + col] : 0u;
    }
    __syncthreads();

    int w = tid >> 5, lane = tid & 31;
    int u = w >> 1, h = w & 1;
    int U = U0 + u, b = U / 14, oy = U % 14;
    int c = h * 32 + lane;

    uint32_t wt[9];
#pragma unroll
    for (int t = 0; t < 9; t++) wt[t] = g_w2p[c * 12 + t];

    bool e0 = (oy == 0), e1 = (oy == 13);
    int v0 = e0 ? 2 : 3, v1 = e1 ? 2 : 3;
    int pw0 = __popc(wt[0]), pw1 = __popc(wt[1]), pw2 = __popc(wt[2]);
    int pw6 = __popc(wt[6]), pw7 = __popc(wt[7]), pw8 = __popc(wt[8]);
    int Ci0 = 96 * v0 + (e0 ? 2 * (pw0 + pw1 + pw2) : 0);
    int Ci1 = 96 * v1 + (e1 ? 2 * (pw6 + pw7 + pw8) : 0);
    int Cl0 = 64 * v0 + (e0 ? 2 * (pw1 + pw2) : 0);    // X=0 edge (dx in {1,2})
    int Cl1 = 64 * v1 + (e1 ? 2 * (pw7 + pw8) : 0);
    int Cr0 = 64 * v0 + (e0 ? 2 * (pw0 + pw1) : 0);    // X=27 edge (dx in {0,1})
    int Cr1 = 64 * v1 + (e1 ? 2 * (pw6 + pw7) : 0);

    int2 th = g_th2[c];
    int T = th.x;
    bool sgn = th.y != 0;
    const uint32_t* tr = &stile[u][0][0];
    uint32_t* outp = ((uint32_t*)g_h2) + (b * 196 + oy * 14) * 2 + h;

#define C2_INT(X, nb) { \
    uint32_t r0a = tr[(X)-1],    r0b = tr[(X)],    r0c = tr[(X)+1]; \
    uint32_t r1a = tr[28+(X)-1], r1b = tr[28+(X)], r1c = tr[28+(X)+1]; \
    uint32_t r2a = tr[56+(X)-1], r2b = tr[56+(X)], r2c = tr[56+(X)+1]; \
    uint32_t r3a = tr[84+(X)-1], r3b = tr[84+(X)], r3c = tr[84+(X)+1]; \
    int a0, a1; \
    POP9_32(a0, r0a^wt[0], r0b^wt[1], r0c^wt[2], r1a^wt[3], r1b^wt[4], r1c^wt[5], \
                r2a^wt[6], r2b^wt[7], r2c^wt[8]); \
    POP9_32(a1, r1a^wt[0], r1b^wt[1], r1c^wt[2], r2a^wt[3], r2b^wt[4], r2c^wt[5], \
                r3a^wt[6], r3b^wt[7], r3c^wt[8]); \
    int d0 = Ci0 - 2 * a0, d1 = Ci1 - 2 * a1; \
    nb = sgn ? (max(d0, d1) >= T) : (min(d0, d1) <= T); }

    bool nb0, nb1;
    {   // X = 0 edge: taps dx in {1,2} read cols 0,1
        int a0 = __popc(tr[0] ^ wt[1]) + __popc(tr[1] ^ wt[2])
               + __popc(tr[28] ^ wt[4]) + __popc(tr[29] ^ wt[5])
               + __popc(tr[56] ^ wt[7]) + __popc(tr[57] ^ wt[8]);
        int a1 = __popc(tr[28] ^ wt[1]) + __popc(tr[29] ^ wt[2])
               + __popc(tr[56] ^ wt[4]) + __popc(tr[57] ^ wt[5])
               + __popc(tr[84] ^ wt[7]) + __popc(tr[85] ^ wt[8]);
        int d0 = Cl0 - 2 * a0, d1 = Cl1 - 2 * a1;
        nb0 = sgn ? (max(d0, d1) >= T) : (min(d0, d1) <= T);
    }
    C2_INT(1, nb1);
    uint32_t bal = __ballot_sync(0xffffffffu, nb0 | nb1);
    if (lane == 0) outp[0] = bal;

#pragma unroll 2
    for (int ox = 1; ox <= 12; ox++) {
        C2_INT(2 * ox, nb0);
        C2_INT(2 * ox + 1, nb1);
        bal = __ballot_sync(0xffffffffu, nb0 | nb1);
        if (lane == 0) outp[2 * ox] = bal;
    }

    C2_INT(26, nb0);
    {   // X = 27 edge: taps dx in {0,1} read cols 26,27
        int a0 = __popc(tr[26] ^ wt[0]) + __popc(tr[27] ^ wt[1])
               + __popc(tr[54] ^ wt[3]) + __popc(tr[55] ^ wt[4])
               + __popc(tr[82] ^ wt[6]) + __popc(tr[83] ^ wt[7]);
        int a1 = __popc(tr[54] ^ wt[0]) + __popc(tr[55] ^ wt[1])
               + __popc(tr[82] ^ wt[3]) + __popc(tr[83] ^ wt[4])
               + __popc(tr[110] ^ wt[6]) + __popc(tr[111] ^ wt[7]);
        int d0 = Cr0 - 2 * a0, d1 = Cr1 - 2 * a1;
        nb1 = sgn ? (max(d0, d1) >= T) : (min(d0, d1) <= T);
    }
    bal = __ballot_sync(0xffffffffu, nb0 | nb1);
    if (lane == 0) outp[26] = bal;
#undef C2_INT
}

// ---------------- block2: warp/(img,row,half), lane = channel, CSA popc ----------------
__global__ void __launch_bounds__(256) conv3_kernel() {
    __shared__ unsigned long long stile[4][4][14];     // 4 units x 4 input rows x 14 cols
    int tid = threadIdx.x;
    int U0 = blockIdx.x * 4;
    for (int i = tid; i < 224; i += 256) {
        int u = i / 56, r = i % 56, j = r / 14, col = r % 14;
        int U = U0 + u, b = U / 7, oy = U % 7;
        int ir = 2 * oy - 1 + j;
        stile[u][j][col] = (ir >= 0 && ir < 14) ? g_h2[b * 196 + ir * 14 + col] : 0ull;
    }
    __syncthreads();

    int w = tid >> 5, lane = tid & 31;
    int u = w >> 1, h = w & 1;
    int U = U0 + u, b = U / 7, oy = U % 7;
    int c = h * 32 + lane;

    unsigned long long wt[9];
#pragma unroll
    for (int t = 0; t < 9; t++) wt[t] = g_w3p[c * 10 + t];

    bool e0 = (oy == 0), e1 = (oy == 6);
    int v0 = e0 ? 2 : 3, v1 = e1 ? 2 : 3;
    int pw0 = __popcll(wt[0]), pw1 = __popcll(wt[1]), pw2 = __popcll(wt[2]);
    int pw6 = __popcll(wt[6]), pw7 = __popcll(wt[7]), pw8 = __popcll(wt[8]);
    int Ci0 = 192 * v0 + (e0 ? 2 * (pw0 + pw1 + pw2) : 0);
    int Ci1 = 192 * v1 + (e1 ? 2 * (pw6 + pw7 + pw8) : 0);
    int Cl0 = 128 * v0 + (e0 ? 2 * (pw1 + pw2) : 0);
    int Cl1 = 128 * v1 + (e1 ? 2 * (pw7 + pw8) : 0);
    int Cr0 = 128 * v0 + (e0 ? 2 * (pw0 + pw1) : 0);
    int Cr1 = 128 * v1 + (e1 ? 2 * (pw6 + pw7) : 0);

    int2 th = g_th3[c];
    int T = th.x;
    bool sgn = th.y != 0;
    const unsigned long long* tr = &stile[u][0][0];   // row stride 14
    uint32_t* outp = g_h3u + (b * 49 + oy * 7) * 2 + h;

#define C3_INT(X, nb) { \
    unsigned long long r0a = tr[(X)-1],    r0b = tr[(X)],    r0c = tr[(X)+1]; \
    unsigned long long r1a = tr[14+(X)-1], r1b = tr[14+(X)], r1c = tr[14+(X)+1]; \
    unsigned long long r2a = tr[28+(X)-1], r2b = tr[28+(X)], r2c = tr[28+(X)+1]; \
    unsigned long long r3a = tr[42+(X)-1], r3b = tr[42+(X)], r3c = tr[42+(X)+1]; \
    int a0, a1; \
    POP9_64(a0, r0a^wt[0], r0b^wt[1], r0c^wt[2], r1a^wt[3], r1b^wt[4], r1c^wt[5], \
                r2a^wt[6], r2b^wt[7], r2c^wt[8]); \
    POP9_64(a1, r1a^wt[0], r1b^wt[1], r1c^wt[2], r2a^wt[3], r2b^wt[4], r2c^wt[5], \
                r3a^wt[6], r3b^wt[7], r3c^wt[8]); \
    int d0 = Ci0 - 2 * a0, d1 = Ci1 - 2 * a1; \
    nb = sgn ? (max(d0, d1) >= T) : (min(d0, d1) <= T); }

    bool nb0, nb1;
    {   // X = 0 edge
        int a0 = __popcll(tr[0] ^ wt[1]) + __popcll(tr[1] ^ wt[2])
               + __popcll(tr[14] ^ wt[4]) + __popcll(tr[15] ^ wt[5])
               + __popcll(tr[28] ^ wt[7]) + __popcll(tr[29] ^ wt[8]);
        int a1 = __popcll(tr[14] ^ wt[1]) + __popcll(tr[15] ^ wt[2])
               + __popcll(tr[28] ^ wt[4]) + __popcll(tr[29] ^ wt[5])
               + __popcll(tr[42] ^ wt[7]) + __popcll(tr[43] ^ wt[8]);
        int d0 = Cl0 - 2 * a0, d1 = Cl1 - 2 * a1;
        nb0 = sgn ? (max(d0, d1) >= T) : (min(d0, d1) <= T);
    }
    C3_INT(1, nb1);
    uint32_t bal = __ballot_sync(0xffffffffu, nb0 | nb1);
    if (lane == 0) outp[0] = bal;

#pragma unroll 2
    for (int ox = 1; ox <= 5; ox++) {
        C3_INT(2 * ox, nb0);
        C3_INT(2 * ox + 1, nb1);
        bal = __ballot_sync(0xffffffffu, nb0 | nb1);
        if (lane == 0) outp[2 * ox] = bal;
    }

    C3_INT(12, nb0);
    {   // X = 13 edge
        int a0 = __popcll(tr[12] ^ wt[0]) + __popcll(tr[13] ^ wt[1])
               + __popcll(tr[26] ^ wt[3]) + __popcll(tr[27] ^ wt[4])
               + __popcll(tr[40] ^ wt[6]) + __popcll(tr[41] ^ wt[7]);
        int a1 = __popcll(tr[26] ^ wt[0]) + __popcll(tr[27] ^ wt[1])
               + __popcll(tr[40] ^ wt[3]) + __popcll(tr[41] ^ wt[4])
               + __popcll(tr[54] ^ wt[6]) + __popcll(tr[55] ^ wt[7]);
        int d0 = Cr0 - 2 * a0, d1 = Cr1 - 2 * a1;
        nb1 = sgn ? (max(d0, d1) >= T) : (min(d0, d1) <= T);
    }
    bal = __ballot_sync(0xffffffffu, nb0 | nb1);
    if (lane == 0) outp[12] = bal;
#undef C3_INT
}

// ---------------- classifier ----------------
__global__ void __launch_bounds__(256) fc_kernel(const float* __restrict__ w_head,
                                                 const float* __restrict__ b_head,
                                                 float* __restrict__ out) {
    __shared__ unsigned long long xrow[49];
    __shared__ float h4[256];
    int b = blockIdx.x, t = threadIdx.x;
    if (t < 49) {
        uint32_t lo = g_h3u[(b * 49 + t) * 2];
        uint32_t hi = g_h3u[(b * 49 + t) * 2 + 1];
        xrow[t] = (unsigned long long)lo | ((unsigned long long)hi << 32);
    }
    __syncthreads();

    const unsigned long long* wr = g_wfcp + t * 49;
    int acc = 0;
#pragma unroll
    for (int p = 0; p < 49; p++) acc += __popcll(xrow[p] ^ wr[p]);
    float4 bn = g_bn4[t];
    h4[t] = ((float)(3136 - 2 * acc) - bn.y) * bn.x + bn.z;
    __syncthreads();

    if (t < 10) {
        float s = b_head[t];
        const float* wh = w_head + t * 256;
#pragma unroll 8
        for (int c = 0; c < 256; c++) s += h4[c] * wh[c];
        out[b * 10 + t] = s;
    }
}

// ---------------- launch ----------------
extern "C" void kernel_launch(void* const* d_in, const int* in_sizes, int n_in,
                              void* d_out, int out_size) {
    const float* x      = (const float*)d_in[0];
    const float* w_stem = (const float*)d_in[1];
    const float* g1 = (const float*)d_in[2];
    const float* b1 = (const float*)d_in[3];
    const float* m1 = (const float*)d_in[4];
    const float* v1 = (const float*)d_in[5];
    const float* w2 = (const float*)d_in[6];
    const float* g2 = (const float*)d_in[7];
    const float* b2 = (const float*)d_in[8];
    const float* m2 = (const float*)d_in[9];
    const float* v2 = (const float*)d_in[10];
    const float* w3 = (const float*)d_in[11];
    const float* g3 = (const float*)d_in[12];
    const float* b3 = (const float*)d_in[13];
    const float* m3 = (const float*)d_in[14];
    const float* v3 = (const float*)d_in[15];
    const float* w_fc = (const float*)d_in[16];
    const float* g4 = (const float*)d_in[17];
    const float* b4 = (const float*)d_in[18];
    const float* m4 = (const float*)d_in[19];
    const float* v4 = (const float*)d_in[20];
    const float* w_head = (const float*)d_in[21];
    const float* b_head = (const float*)d_in[22];
    float* out = (float*)d_out;

    pack_kernel<<<57, 256>>>(w2, w3, w_fc, g1, v1, m1, b1, g2, v2, m2, b2,
                             g3, v3, m3, b3, g4, v4, m4, b4);
    stem_kernel<<<(BATCH * 784 * 2) / 256, 256>>>(x, w_stem);
    conv2_kernel<<<(BATCH * 14) / 4, 256>>>();   // 7168 blocks
    conv3_kernel<<<(BATCH * 7) / 4, 256>>>();    // 3584 blocks
    fc_kernel<<<BATCH, 256>>>(w_head, b_head, out);
}

// round 12
// speedup vs baseline: 1.8698x; 1.0405x over previous
#include <cuda_runtime.h>
#include <stdint.h>

#define BATCH 2048
#define EPS 1e-5f

// ---------------- static scratch ----------------
__device__ uint32_t           g_h1[BATCH * 784];        // stem out, 32 ch packed
__device__ unsigned long long g_h2[BATCH * 196];        // block1 out, 64 ch packed (u32 halves)
__device__ uint32_t           g_h3u[BATCH * 49 * 2];    // block2 out, u32 halves
__device__ uint32_t           g_w2p[64 * 12];           // sign(w2), [ch][tap] stride 12
__device__ unsigned long long g_w3p[64 * 10];           // sign(w3), [ch][tap] stride 10
__device__ unsigned long long g_wfcp[256 * 49];         // sign(w_fc)
__device__ float4 g_bn1[32], g_bn4[256];                // (inv, mean, beta, 0)
__device__ int2   g_th2[64], g_th3[64];                 // (integer threshold, sgn)

// carry-save adder compressors (single LOP3 each after ptxas fusion)
#define CSA32(s, c, x, y, z) do { uint32_t _x = (x), _y = (y), _z = (z); \
    (s) = _x ^ _y ^ _z; (c) = (_x & _y) | (_z & (_x | _y)); } while (0)
#define CSA64(s, c, x, y, z) do { unsigned long long _x = (x), _y = (y), _z = (z); \
    (s) = _x ^ _y ^ _z; (c) = (_x & _y) | (_z & (_x | _y)); } while (0)

// popcount of sum of 9 words via full CSA tree: 4 POPC instead of 9
#define POP9_32(res, v0, v1, v2, v3, v4, v5, v6, v7, v8) do { \
    uint32_t _s1, _c1, _s2, _c2, _s3, _c3, _s4, _c4, _s5, _c5; \
    CSA32(_s1, _c1, v0, v1, v2); CSA32(_s2, _c2, v3, v4, v5); CSA32(_s3, _c3, v6, v7, v8); \
    CSA32(_s4, _c4, _s1, _s2, _s3); CSA32(_s5, _c5, _c1, _c2, _c3); \
    (res) = __popc(_s4) + 2 * (__popc(_c4) + __popc(_s5)) + 4 * __popc(_c5); } while (0)
#define POP9_64(res, v0, v1, v2, v3, v4, v5, v6, v7, v8) do { \
    unsigned long long _s1, _c1, _s2, _c2, _s3, _c3, _s4, _c4, _s5, _c5; \
    CSA64(_s1, _c1, v0, v1, v2); CSA64(_s2, _c2, v3, v4, v5); CSA64(_s3, _c3, v6, v7, v8); \
    CSA64(_s4, _c4, _s1, _s2, _s3); CSA64(_s5, _c5, _c1, _c2, _c3); \
    (res) = __popcll(_s4) + 2 * (__popcll(_c4) + __popcll(_s5)) + 4 * __popcll(_c5); } while (0)

// ---------------- packing + BN + integer thresholds ----------------
__global__ void pack_kernel(const float* __restrict__ w2, const float* __restrict__ w3,
                            const float* __restrict__ wfc,
                            const float* __restrict__ g1, const float* __restrict__ v1,
                            const float* __restrict__ m1, const float* __restrict__ b1,
                            const float* __restrict__ g2, const float* __restrict__ v2,
                            const float* __restrict__ m2, const float* __restrict__ b2,
                            const float* __restrict__ g3, const float* __restrict__ v3,
                            const float* __restrict__ m3, const float* __restrict__ b3,
                            const float* __restrict__ g4, const float* __restrict__ v4,
                            const float* __restrict__ m4, const float* __restrict__ b4) {
    int idx = blockIdx.x * 256 + threadIdx.x;
    if (idx < 768) {                                   // w2: [64,32,3,3] -> stride 12
        int o = idx / 12, t = idx % 12;
        uint32_t bits = 0;
        if (t < 9)
            for (int c = 0; c < 32; c++)
                bits |= (w2[o * 288 + c * 9 + t] >= 0.f ? 1u : 0u) << c;
        g_w2p[idx] = bits;
    } else if (idx < 1408) {                           // w3: [64,64,3,3] -> stride 10
        int j = idx - 768; int o = j / 10, t = j % 10;
        unsigned long long bits = 0;
        if (t < 9)
            for (int c = 0; c < 64; c++)
                bits |= (unsigned long long)(w3[o * 576 + c * 9 + t] >= 0.f) << c;
        g_w3p[j] = bits;
    } else if (idx < 13952) {                          // w_fc: [256,3136]
        int j = idx - 1408; int o = j / 49, p = j % 49;
        unsigned long long bits = 0;
        for (int c = 0; c < 64; c++)
            bits |= (unsigned long long)(wfc[o * 3136 + c * 49 + p] >= 0.f) << c;
        g_wfcp[j] = bits;
    } else if (idx < 13984) {
        int c = idx - 13952;
        g_bn1[c] = make_float4(g1[c] / sqrtf(v1[c] + EPS), m1[c], b1[c], 0.f);
    } else if (idx < 14240) {
        int c = idx - 13984;
        g_bn4[c] = make_float4(g4[c] / sqrtf(v4[c] + EPS), m4[c], b4[c], 0.f);
    } else if (idx < 14304) {                          // conv2 thresholds (d in [-288,288], even)
        int c = idx - 14240;
        float inv = g2[c] / sqrtf(v2[c] + EPS), m = m2[c], be = b2[c];
        int sgn = (inv >= 0.f) ? 1 : 0;
        int T;
        if (sgn) {
            T = 10000;
            for (int d = -288; d <= 288; d += 2)
                if (((float)d - m) * inv + be >= 0.f) { T = d; break; }
        } else {
            T = -10000;
            for (int d = 288; d >= -288; d -= 2)
                if (((float)d - m) * inv + be >= 0.f) { T = d; break; }
        }
        g_th2[c] = make_int2(T, sgn);
    } else if (idx < 14368) {                          // conv3 thresholds (d in [-576,576], even)
        int c = idx - 14304;
        float inv = g3[c] / sqrtf(v3[c] + EPS), m = m3[c], be = b3[c];
        int sgn = (inv >= 0.f) ? 1 : 0;
        int T;
        if (sgn) {
            T = 10000;
            for (int d = -576; d <= 576; d += 2)
                if (((float)d - m) * inv + be >= 0.f) { T = d; break; }
        } else {
            T = -10000;
            for (int d = 576; d >= -576; d -= 2)
                if (((float)d - m) * inv + be >= 0.f) { T = d; break; }
        }
        g_th3[c] = make_int2(T, sgn);
    }
}

// ---------------- stem: warp per output row, lane = channel ----------------
// block = 224 threads (7 warps); block q covers output rows 7q..7q+6 of one image
__global__ void __launch_bounds__(224) stem_kernel(const float* __restrict__ x,
                                                   const float* __restrict__ ws) {
    __shared__ float tile[9][32];                      // rows y0-1..y0+7, cols x=-1..28 (shift +1)
    int tid = threadIdx.x;
    int img = blockIdx.x >> 2, q = blockIdx.x & 3;
    int y0 = q * 7;
    const float* xb = x + img * 784;

    for (int i = tid; i < 270; i += 224) {
        int r = i / 30, col = i % 30;
        int yy = y0 - 1 + r, xc = col - 1;
        float v = 0.f;
        if (yy >= 0 && yy < 28 && xc >= 0 && xc < 28) v = xb[yy * 28 + xc];
        tile[r][col] = v;
    }

    int wid = tid >> 5, lane = tid & 31;
    float wt[9];
#pragma unroll
    for (int k = 0; k < 9; k++) wt[k] = ws[lane * 9 + k];
    float4 bn = g_bn1[lane];
    __syncthreads();

    int y = y0 + wid;
    uint32_t* orow = g_h1 + img * 784 + y * 28;

#pragma unroll 2
    for (int xx = 0; xx < 28; xx++) {
        float s = 0.f;
#pragma unroll
        for (int dy = 0; dy < 3; dy++)
#pragma unroll
            for (int dx = 0; dx < 3; dx++)
                s += wt[dy * 3 + dx] * tile[wid + dy][xx + dx];
        float v = (s - bn.y) * bn.x + bn.z;
        uint32_t bits = __ballot_sync(0xffffffffu, v >= 0.f);
        if (lane == 0) orow[xx] = bits;
    }
}

// ---------------- block1: warp/(img,row,half), lane = channel, CSA popc ----------------
__global__ void __launch_bounds__(256, 4) conv2_kernel() {
    __shared__ uint32_t stile[4][4][28];               // 4 units x 4 input rows x 28 cols
    int tid = threadIdx.x;
    int U0 = blockIdx.x * 4;
    for (int i = tid; i < 448; i += 256) {
        int u = i / 112, r = i % 112, j = r / 28, col = r % 28;
        int U = U0 + u, b = U / 14, oy = U % 14;
        int ir = 2 * oy - 1 + j;
        stile[u][j][col] = (ir >= 0 && ir < 28) ? g_h1[b * 784 + ir * 28 + col] : 0u;
    }
    __syncthreads();

    int w = tid >> 5, lane = tid & 31;
    int u = w >> 1, h = w & 1;
    int U = U0 + u, b = U / 14, oy = U % 14;
    int c = h * 32 + lane;

    uint32_t wt[9];
#pragma unroll
    for (int t = 0; t < 9; t++) wt[t] = g_w2p[c * 12 + t];

    bool e0 = (oy == 0), e1 = (oy == 13);
    int v0 = e0 ? 2 : 3, v1 = e1 ? 2 : 3;
    int pw0 = __popc(wt[0]), pw1 = __popc(wt[1]), pw2 = __popc(wt[2]);
    int pw6 = __popc(wt[6]), pw7 = __popc(wt[7]), pw8 = __popc(wt[8]);
    int Ci0 = 96 * v0 + (e0 ? 2 * (pw0 + pw1 + pw2) : 0);
    int Ci1 = 96 * v1 + (e1 ? 2 * (pw6 + pw7 + pw8) : 0);
    int Cl0 = 64 * v0 + (e0 ? 2 * (pw1 + pw2) : 0);    // X=0 edge (dx in {1,2})
    int Cl1 = 64 * v1 + (e1 ? 2 * (pw7 + pw8) : 0);
    int Cr0 = 64 * v0 + (e0 ? 2 * (pw0 + pw1) : 0);    // X=27 edge (dx in {0,1})
    int Cr1 = 64 * v1 + (e1 ? 2 * (pw6 + pw7) : 0);

    int2 th = g_th2[c];
    int T = th.x;
    bool sgn = th.y != 0;
    const uint32_t* tr = &stile[u][0][0];
    uint32_t* outp = ((uint32_t*)g_h2) + (b * 196 + oy * 14) * 2 + h;

#define C2_INT(X, nb) { \
    uint32_t r0a = tr[(X)-1],    r0b = tr[(X)],    r0c = tr[(X)+1]; \
    uint32_t r1a = tr[28+(X)-1], r1b = tr[28+(X)], r1c = tr[28+(X)+1]; \
    uint32_t r2a = tr[56+(X)-1], r2b = tr[56+(X)], r2c = tr[56+(X)+1]; \
    uint32_t r3a = tr[84+(X)-1], r3b = tr[84+(X)], r3c = tr[84+(X)+1]; \
    int a0, a1; \
    POP9_32(a0, r0a^wt[0], r0b^wt[1], r0c^wt[2], r1a^wt[3], r1b^wt[4], r1c^wt[5], \
                r2a^wt[6], r2b^wt[7], r2c^wt[8]); \
    POP9_32(a1, r1a^wt[0], r1b^wt[1], r1c^wt[2], r2a^wt[3], r2b^wt[4], r2c^wt[5], \
                r3a^wt[6], r3b^wt[7], r3c^wt[8]); \
    int d0 = Ci0 - 2 * a0, d1 = Ci1 - 2 * a1; \
    nb = sgn ? (max(d0, d1) >= T) : (min(d0, d1) <= T); }

    bool nb0, nb1;
    {   // X = 0 edge: taps dx in {1,2} read cols 0,1
        int a0 = __popc(tr[0] ^ wt[1]) + __popc(tr[1] ^ wt[2])
               + __popc(tr[28] ^ wt[4]) + __popc(tr[29] ^ wt[5])
               + __popc(tr[56] ^ wt[7]) + __popc(tr[57] ^ wt[8]);
        int a1 = __popc(tr[28] ^ wt[1]) + __popc(tr[29] ^ wt[2])
               + __popc(tr[56] ^ wt[4]) + __popc(tr[57] ^ wt[5])
               + __popc(tr[84] ^ wt[7]) + __popc(tr[85] ^ wt[8]);
        int d0 = Cl0 - 2 * a0, d1 = Cl1 - 2 * a1;
        nb0 = sgn ? (max(d0, d1) >= T) : (min(d0, d1) <= T);
    }
    C2_INT(1, nb1);
    uint32_t bal = __ballot_sync(0xffffffffu, nb0 | nb1);
    if (lane == 0) outp[0] = bal;

#pragma unroll 2
    for (int ox = 1; ox <= 12; ox++) {
        C2_INT(2 * ox, nb0);
        C2_INT(2 * ox + 1, nb1);
        bal = __ballot_sync(0xffffffffu, nb0 | nb1);
        if (lane == 0) outp[2 * ox] = bal;
    }

    C2_INT(26, nb0);
    {   // X = 27 edge: taps dx in {0,1} read cols 26,27
        int a0 = __popc(tr[26] ^ wt[0]) + __popc(tr[27] ^ wt[1])
               + __popc(tr[54] ^ wt[3]) + __popc(tr[55] ^ wt[4])
               + __popc(tr[82] ^ wt[6]) + __popc(tr[83] ^ wt[7]);
        int a1 = __popc(tr[54] ^ wt[0]) + __popc(tr[55] ^ wt[1])
               + __popc(tr[82] ^ wt[3]) + __popc(tr[83] ^ wt[4])
               + __popc(tr[110] ^ wt[6]) + __popc(tr[111] ^ wt[7]);
        int d0 = Cr0 - 2 * a0, d1 = Cr1 - 2 * a1;
        nb1 = sgn ? (max(d0, d1) >= T) : (min(d0, d1) <= T);
    }
    bal = __ballot_sync(0xffffffffu, nb0 | nb1);
    if (lane == 0) outp[26] = bal;
#undef C2_INT
}

// ---------------- block2: warp/(img,row,half), lane = channel, CSA popc ----------------
__global__ void __launch_bounds__(256, 4) conv3_kernel() {
    __shared__ unsigned long long stile[4][4][14];     // 4 units x 4 input rows x 14 cols
    int tid = threadIdx.x;
    int U0 = blockIdx.x * 4;
    for (int i = tid; i < 224; i += 256) {
        int u = i / 56, r = i % 56, j = r / 14, col = r % 14;
        int U = U0 + u, b = U / 7, oy = U % 7;
        int ir = 2 * oy - 1 + j;
        stile[u][j][col] = (ir >= 0 && ir < 14) ? g_h2[b * 196 + ir * 14 + col] : 0ull;
    }
    __syncthreads();

    int w = tid >> 5, lane = tid & 31;
    int u = w >> 1, h = w & 1;
    int U = U0 + u, b = U / 7, oy = U % 7;
    int c = h * 32 + lane;

    unsigned long long wt[9];
#pragma unroll
    for (int t = 0; t < 9; t++) wt[t] = g_w3p[c * 10 + t];

    bool e0 = (oy == 0), e1 = (oy == 6);
    int v0 = e0 ? 2 : 3, v1 = e1 ? 2 : 3;
    int pw0 = __popcll(wt[0]), pw1 = __popcll(wt[1]), pw2 = __popcll(wt[2]);
    int pw6 = __popcll(wt[6]), pw7 = __popcll(wt[7]), pw8 = __popcll(wt[8]);
    int Ci0 = 192 * v0 + (e0 ? 2 * (pw0 + pw1 + pw2) : 0);
    int Ci1 = 192 * v1 + (e1 ? 2 * (pw6 + pw7 + pw8) : 0);
    int Cl0 = 128 * v0 + (e0 ? 2 * (pw1 + pw2) : 0);
    int Cl1 = 128 * v1 + (e1 ? 2 * (pw7 + pw8) : 0);
    int Cr0 = 128 * v0 + (e0 ? 2 * (pw0 + pw1) : 0);
    int Cr1 = 128 * v1 + (e1 ? 2 * (pw6 + pw7) : 0);

    int2 th = g_th3[c];
    int T = th.x;
    bool sgn = th.y != 0;
    const unsigned long long* tr = &stile[u][0][0];   // row stride 14
    uint32_t* outp = g_h3u + (b * 49 + oy * 7) * 2 + h;

#define C3_INT(X, nb) { \
    unsigned long long r0a = tr[(X)-1],    r0b = tr[(X)],    r0c = tr[(X)+1]; \
    unsigned long long r1a = tr[14+(X)-1], r1b = tr[14+(X)], r1c = tr[14+(X)+1]; \
    unsigned long long r2a = tr[28+(X)-1], r2b = tr[28+(X)], r2c = tr[28+(X)+1]; \
    unsigned long long r3a = tr[42+(X)-1], r3b = tr[42+(X)], r3c = tr[42+(X)+1]; \
    int a0, a1; \
    POP9_64(a0, r0a^wt[0], r0b^wt[1], r0c^wt[2], r1a^wt[3], r1b^wt[4], r1c^wt[5], \
                r2a^wt[6], r2b^wt[7], r2c^wt[8]); \
    POP9_64(a1, r1a^wt[0], r1b^wt[1], r1c^wt[2], r2a^wt[3], r2b^wt[4], r2c^wt[5], \
                r3a^wt[6], r3b^wt[7], r3c^wt[8]); \
    int d0 = Ci0 - 2 * a0, d1 = Ci1 - 2 * a1; \
    nb = sgn ? (max(d0, d1) >= T) : (min(d0, d1) <= T); }

    bool nb0, nb1;
    {   // X = 0 edge
        int a0 = __popcll(tr[0] ^ wt[1]) + __popcll(tr[1] ^ wt[2])
               + __popcll(tr[14] ^ wt[4]) + __popcll(tr[15] ^ wt[5])
               + __popcll(tr[28] ^ wt[7]) + __popcll(tr[29] ^ wt[8]);
        int a1 = __popcll(tr[14] ^ wt[1]) + __popcll(tr[15] ^ wt[2])
               + __popcll(tr[28] ^ wt[4]) + __popcll(tr[29] ^ wt[5])
               + __popcll(tr[42] ^ wt[7]) + __popcll(tr[43] ^ wt[8]);
        int d0 = Cl0 - 2 * a0, d1 = Cl1 - 2 * a1;
        nb0 = sgn ? (max(d0, d1) >= T) : (min(d0, d1) <= T);
    }
    C3_INT(1, nb1);
    uint32_t bal = __ballot_sync(0xffffffffu, nb0 | nb1);
    if (lane == 0) outp[0] = bal;

#pragma unroll 2
    for (int ox = 1; ox <= 5; ox++) {
        C3_INT(2 * ox, nb0);
        C3_INT(2 * ox + 1, nb1);
        bal = __ballot_sync(0xffffffffu, nb0 | nb1);
        if (lane == 0) outp[2 * ox] = bal;
    }

    C3_INT(12, nb0);
    {   // X = 13 edge
        int a0 = __popcll(tr[12] ^ wt[0]) + __popcll(tr[13] ^ wt[1])
               + __popcll(tr[26] ^ wt[3]) + __popcll(tr[27] ^ wt[4])
               + __popcll(tr[40] ^ wt[6]) + __popcll(tr[41] ^ wt[7]);
        int a1 = __popcll(tr[26] ^ wt[0]) + __popcll(tr[27] ^ wt[1])
               + __popcll(tr[40] ^ wt[3]) + __popcll(tr[41] ^ wt[4])
               + __popcll(tr[54] ^ wt[6]) + __popcll(tr[55] ^ wt[7]);
        int d0 = Cr0 - 2 * a0, d1 = Cr1 - 2 * a1;
        nb1 = sgn ? (max(d0, d1) >= T) : (min(d0, d1) <= T);
    }
    bal = __ballot_sync(0xffffffffu, nb0 | nb1);
    if (lane == 0) outp[12] = bal;
#undef C3_INT
}

// ---------------- classifier ----------------
__global__ void __launch_bounds__(256) fc_kernel(const float* __restrict__ w_head,
                                                 const float* __restrict__ b_head,
                                                 float* __restrict__ out) {
    __shared__ unsigned long long xrow[49];
    __shared__ float h4[256];
    int b = blockIdx.x, t = threadIdx.x;
    if (t < 49) {
        uint32_t lo = g_h3u[(b * 49 + t) * 2];
        uint32_t hi = g_h3u[(b * 49 + t) * 2 + 1];
        xrow[t] = (unsigned long long)lo | ((unsigned long long)hi << 32);
    }
    __syncthreads();

    const unsigned long long* wr = g_wfcp + t * 49;
    int acc = 0;
#pragma unroll
    for (int p = 0; p < 49; p++) acc += __popcll(xrow[p] ^ wr[p]);
    float4 bn = g_bn4[t];
    h4[t] = ((float)(3136 - 2 * acc) - bn.y) * bn.x + bn.z;
    __syncthreads();

    if (t < 10) {
        float s = b_head[t];
        const float* wh = w_head + t * 256;
#pragma unroll 8
        for (int c = 0; c < 256; c++) s += h4[c] * wh[c];
        out[b * 10 + t] = s;
    }
}

// ---------------- launch ----------------
extern "C" void kernel_launch(void* const* d_in, const int* in_sizes, int n_in,
                              void* d_out, int out_size) {
    const float* x      = (const float*)d_in[0];
    const float* w_stem = (const float*)d_in[1];
    const float* g1 = (const float*)d_in[2];
    const float* b1 = (const float*)d_in[3];
    const float* m1 = (const float*)d_in[4];
    const float* v1 = (const float*)d_in[5];
    const float* w2 = (const float*)d_in[6];
    const float* g2 = (const float*)d_in[7];
    const float* b2 = (const float*)d_in[8];
    const float* m2 = (const float*)d_in[9];
    const float* v2 = (const float*)d_in[10];
    const float* w3 = (const float*)d_in[11];
    const float* g3 = (const float*)d_in[12];
    const float* b3 = (const float*)d_in[13];
    const float* m3 = (const float*)d_in[14];
    const float* v3 = (const float*)d_in[15];
    const float* w_fc = (const float*)d_in[16];
    const float* g4 = (const float*)d_in[17];
    const float* b4 = (const float*)d_in[18];
    const float* m4 = (const float*)d_in[19];
    const float* v4 = (const float*)d_in[20];
    const float* w_head = (const float*)d_in[21];
    const float* b_head = (const float*)d_in[22];
    float* out = (float*)d_out;

    pack_kernel<<<57, 256>>>(w2, w3, w_fc, g1, v1, m1, b1, g2, v2, m2, b2,
                             g3, v3, m3, b3, g4, v4, m4, b4);
    stem_kernel<<<BATCH * 4, 224>>>(x, w_stem);      // 8192 blocks, 7 warps each
    conv2_kernel<<<(BATCH * 14) / 4, 256>>>();       // 7168 blocks
    conv3_kernel<<<(BATCH * 7) / 4, 256>>>();        // 3584 blocks
    fc_kernel<<<BATCH, 256>>>(w_head, b_head, out);
}

// round 13
// speedup vs baseline: 1.9082x; 1.0205x over previous
#include <cuda_runtime.h>
#include <stdint.h>

#define BATCH 2048
#define EPS 1e-5f

// ---------------- static scratch ----------------
__device__ uint32_t           g_h1[BATCH * 784];        // stem out, 32 ch packed
__device__ unsigned long long g_h2[BATCH * 196];        // block1 out, 64 ch packed (u32 halves)
__device__ uint32_t           g_h3u[BATCH * 49 * 2];    // block2 out, u32 halves
__device__ uint32_t           g_w2p[64 * 12];           // sign(w2), [ch][tap] stride 12
__device__ unsigned long long g_w3p[64 * 10];           // sign(w3), [ch][tap] stride 10
__device__ unsigned long long g_wfcp[256 * 49];         // sign(w_fc)
__device__ float4 g_bn1[32], g_bn4[256];                // (inv, mean, beta, 0)
__device__ int2   g_th2[64], g_th3[64];                 // (integer threshold, sgn)

// carry-save adder compressors (single LOP3 each after ptxas fusion)
#define CSA32(s, c, x, y, z) do { uint32_t _x = (x), _y = (y), _z = (z); \
    (s) = _x ^ _y ^ _z; (c) = (_x & _y) | (_z & (_x | _y)); } while (0)
#define CSA64(s, c, x, y, z) do { unsigned long long _x = (x), _y = (y), _z = (z); \
    (s) = _x ^ _y ^ _z; (c) = (_x & _y) | (_z & (_x | _y)); } while (0)

// popcount of sum of 9 words via full CSA tree: 4 POPC instead of 9
#define POP9_32(res, v0, v1, v2, v3, v4, v5, v6, v7, v8) do { \
    uint32_t _s1, _c1, _s2, _c2, _s3, _c3, _s4, _c4, _s5, _c5; \
    CSA32(_s1, _c1, v0, v1, v2); CSA32(_s2, _c2, v3, v4, v5); CSA32(_s3, _c3, v6, v7, v8); \
    CSA32(_s4, _c4, _s1, _s2, _s3); CSA32(_s5, _c5, _c1, _c2, _c3); \
    (res) = __popc(_s4) + 2 * (__popc(_c4) + __popc(_s5)) + 4 * __popc(_c5); } while (0)
#define POP9_64(res, v0, v1, v2, v3, v4, v5, v6, v7, v8) do { \
    unsigned long long _s1, _c1, _s2, _c2, _s3, _c3, _s4, _c4, _s5, _c5; \
    CSA64(_s1, _c1, v0, v1, v2); CSA64(_s2, _c2, v3, v4, v5); CSA64(_s3, _c3, v6, v7, v8); \
    CSA64(_s4, _c4, _s1, _s2, _s3); CSA64(_s5, _c5, _c1, _c2, _c3); \
    (res) = __popcll(_s4) + 2 * (__popcll(_c4) + __popcll(_s5)) + 4 * __popcll(_c5); } while (0)

// ---------------- packing + BN + integer thresholds ----------------
__global__ void pack_kernel(const float* __restrict__ w2, const float* __restrict__ w3,
                            const float* __restrict__ wfc,
                            const float* __restrict__ g1, const float* __restrict__ v1,
                            const float* __restrict__ m1, const float* __restrict__ b1,
                            const float* __restrict__ g2, const float* __restrict__ v2,
                            const float* __restrict__ m2, const float* __restrict__ b2,
                            const float* __restrict__ g3, const float* __restrict__ v3,
                            const float* __restrict__ m3, const float* __restrict__ b3,
                            const float* __restrict__ g4, const float* __restrict__ v4,
                            const float* __restrict__ m4, const float* __restrict__ b4) {
    int idx = blockIdx.x * 256 + threadIdx.x;
    if (idx < 768) {                                   // w2: [64,32,3,3] -> stride 12
        int o = idx / 12, t = idx % 12;
        uint32_t bits = 0;
        if (t < 9)
            for (int c = 0; c < 32; c++)
                bits |= (w2[o * 288 + c * 9 + t] >= 0.f ? 1u : 0u) << c;
        g_w2p[idx] = bits;
    } else if (idx < 1408) {                           // w3: [64,64,3,3] -> stride 10
        int j = idx - 768; int o = j / 10, t = j % 10;
        unsigned long long bits = 0;
        if (t < 9)
            for (int c = 0; c < 64; c++)
                bits |= (unsigned long long)(w3[o * 576 + c * 9 + t] >= 0.f) << c;
        g_w3p[j] = bits;
    } else if (idx < 13952) {                          // w_fc: [256,3136]
        int j = idx - 1408; int o = j / 49, p = j % 49;
        unsigned long long bits = 0;
        for (int c = 0; c < 64; c++)
            bits |= (unsigned long long)(wfc[o * 3136 + c * 49 + p] >= 0.f) << c;
        g_wfcp[j] = bits;
    } else if (idx < 13984) {
        int c = idx - 13952;
        g_bn1[c] = make_float4(g1[c] / sqrtf(v1[c] + EPS), m1[c], b1[c], 0.f);
    } else if (idx < 14240) {
        int c = idx - 13984;
        g_bn4[c] = make_float4(g4[c] / sqrtf(v4[c] + EPS), m4[c], b4[c], 0.f);
    } else if (idx < 14304) {                          // conv2 thresholds (d in [-288,288], even)
        int c = idx - 14240;
        float inv = g2[c] / sqrtf(v2[c] + EPS), m = m2[c], be = b2[c];
        int sgn = (inv >= 0.f) ? 1 : 0;
        int T;
        if (sgn) {
            T = 10000;
            for (int d = -288; d <= 288; d += 2)
                if (((float)d - m) * inv + be >= 0.f) { T = d; break; }
        } else {
            T = -10000;
            for (int d = 288; d >= -288; d -= 2)
                if (((float)d - m) * inv + be >= 0.f) { T = d; break; }
        }
        g_th2[c] = make_int2(T, sgn);
    } else if (idx < 14368) {                          // conv3 thresholds (d in [-576,576], even)
        int c = idx - 14304;
        float inv = g3[c] / sqrtf(v3[c] + EPS), m = m3[c], be = b3[c];
        int sgn = (inv >= 0.f) ? 1 : 0;
        int T;
        if (sgn) {
            T = 10000;
            for (int d = -576; d <= 576; d += 2)
                if (((float)d - m) * inv + be >= 0.f) { T = d; break; }
        } else {
            T = -10000;
            for (int d = 576; d >= -576; d -= 2)
                if (((float)d - m) * inv + be >= 0.f) { T = d; break; }
        }
        g_th3[c] = make_int2(T, sgn);
    }
}

// ---------------- stem: warp per output row, lane = channel, sliding cols ----------------
// block = 224 threads (7 warps); block q covers output rows 7q..7q+6 of one image
__global__ void __launch_bounds__(224) stem_kernel(const float* __restrict__ x,
                                                   const float* __restrict__ ws) {
    __shared__ float tile[9][32];                      // rows y0-1..y0+7, cols x=-1..28 (shift +1)
    int tid = threadIdx.x;
    int img = blockIdx.x >> 2, q = blockIdx.x & 3;
    int y0 = q * 7;
    const float* xb = x + img * 784;

    for (int i = tid; i < 270; i += 224) {
        int r = i / 30, col = i % 30;
        int yy = y0 - 1 + r, xc = col - 1;
        float v = 0.f;
        if (yy >= 0 && yy < 28 && xc >= 0 && xc < 28) v = xb[yy * 28 + xc];
        tile[r][col] = v;
    }

    int wid = tid >> 5, lane = tid & 31;
    float wt[9];
#pragma unroll
    for (int k = 0; k < 9; k++) wt[k] = ws[lane * 9 + k];
    float4 bn = g_bn1[lane];
    __syncthreads();

    int y = y0 + wid;
    uint32_t* orow = g_h1 + img * 784 + y * 28;

    // sliding 3-column window, registers renamed by full unroll (no rotation MOVs)
    float a0 = tile[wid][0],     a1 = tile[wid + 1][0],     a2 = tile[wid + 2][0];
    float b0 = tile[wid][1],     b1 = tile[wid + 1][1],     b2 = tile[wid + 2][1];

#pragma unroll
    for (int xx = 0; xx < 28; xx++) {
        float c0 = tile[wid][xx + 2], c1 = tile[wid + 1][xx + 2], c2 = tile[wid + 2][xx + 2];
        // accumulation order identical to previous passing version: k = 0..8
        float s = wt[0] * a0;
        s += wt[1] * b0;  s += wt[2] * c0;
        s += wt[3] * a1;  s += wt[4] * b1;  s += wt[5] * c1;
        s += wt[6] * a2;  s += wt[7] * b2;  s += wt[8] * c2;
        float v = (s - bn.y) * bn.x + bn.z;
        uint32_t bits = __ballot_sync(0xffffffffu, v >= 0.f);
        if (lane == 0) orow[xx] = bits;
        a0 = b0; a1 = b1; a2 = b2;
        b0 = c0; b1 = c1; b2 = c2;
    }
}

// ---------------- block1: warp/(img,row,half), lane = channel, CSA popc ----------------
__global__ void __launch_bounds__(256, 4) conv2_kernel() {
    __shared__ uint32_t stile[4][4][28];               // 4 units x 4 input rows x 28 cols
    int tid = threadIdx.x;
    int U0 = blockIdx.x * 4;
    for (int i = tid; i < 448; i += 256) {
        int u = i / 112, r = i % 112, j = r / 28, col = r % 28;
        int U = U0 + u, b = U / 14, oy = U % 14;
        int ir = 2 * oy - 1 + j;
        stile[u][j][col] = (ir >= 0 && ir < 28) ? g_h1[b * 784 + ir * 28 + col] : 0u;
    }
    __syncthreads();

    int w = tid >> 5, lane = tid & 31;
    int u = w >> 1, h = w & 1;
    int U = U0 + u, b = U / 14, oy = U % 14;
    int c = h * 32 + lane;

    uint32_t wt[9];
#pragma unroll
    for (int t = 0; t < 9; t++) wt[t] = g_w2p[c * 12 + t];

    bool e0 = (oy == 0), e1 = (oy == 13);
    int v0 = e0 ? 2 : 3, v1 = e1 ? 2 : 3;
    int pw0 = __popc(wt[0]), pw1 = __popc(wt[1]), pw2 = __popc(wt[2]);
    int pw6 = __popc(wt[6]), pw7 = __popc(wt[7]), pw8 = __popc(wt[8]);
    int Ci0 = 96 * v0 + (e0 ? 2 * (pw0 + pw1 + pw2) : 0);
    int Ci1 = 96 * v1 + (e1 ? 2 * (pw6 + pw7 + pw8) : 0);
    int Cl0 = 64 * v0 + (e0 ? 2 * (pw1 + pw2) : 0);    // X=0 edge (dx in {1,2})
    int Cl1 = 64 * v1 + (e1 ? 2 * (pw7 + pw8) : 0);
    int Cr0 = 64 * v0 + (e0 ? 2 * (pw0 + pw1) : 0);    // X=27 edge (dx in {0,1})
    int Cr1 = 64 * v1 + (e1 ? 2 * (pw6 + pw7) : 0);

    int2 th = g_th2[c];
    int T = th.x;
    bool sgn = th.y != 0;
    const uint32_t* tr = &stile[u][0][0];
    uint32_t* outp = ((uint32_t*)g_h2) + (b * 196 + oy * 14) * 2 + h;

#define C2_INT(X, nb) { \
    uint32_t r0a = tr[(X)-1],    r0b = tr[(X)],    r0c = tr[(X)+1]; \
    uint32_t r1a = tr[28+(X)-1], r1b = tr[28+(X)], r1c = tr[28+(X)+1]; \
    uint32_t r2a = tr[56+(X)-1], r2b = tr[56+(X)], r2c = tr[56+(X)+1]; \
    uint32_t r3a = tr[84+(X)-1], r3b = tr[84+(X)], r3c = tr[84+(X)+1]; \
    int a0, a1; \
    POP9_32(a0, r0a^wt[0], r0b^wt[1], r0c^wt[2], r1a^wt[3], r1b^wt[4], r1c^wt[5], \
                r2a^wt[6], r2b^wt[7], r2c^wt[8]); \
    POP9_32(a1, r1a^wt[0], r1b^wt[1], r1c^wt[2], r2a^wt[3], r2b^wt[4], r2c^wt[5], \
                r3a^wt[6], r3b^wt[7], r3c^wt[8]); \
    int d0 = Ci0 - 2 * a0, d1 = Ci1 - 2 * a1; \
    nb = sgn ? (max(d0, d1) >= T) : (min(d0, d1) <= T); }

    bool nb0, nb1;
    {   // X = 0 edge: taps dx in {1,2} read cols 0,1
        int a0 = __popc(tr[0] ^ wt[1]) + __popc(tr[1] ^ wt[2])
               + __popc(tr[28] ^ wt[4]) + __popc(tr[29] ^ wt[5])
               + __popc(tr[56] ^ wt[7]) + __popc(tr[57] ^ wt[8]);
        int a1 = __popc(tr[28] ^ wt[1]) + __popc(tr[29] ^ wt[2])
               + __popc(tr[56] ^ wt[4]) + __popc(tr[57] ^ wt[5])
               + __popc(tr[84] ^ wt[7]) + __popc(tr[85] ^ wt[8]);
        int d0 = Cl0 - 2 * a0, d1 = Cl1 - 2 * a1;
        nb0 = sgn ? (max(d0, d1) >= T) : (min(d0, d1) <= T);
    }
    C2_INT(1, nb1);
    uint32_t bal = __ballot_sync(0xffffffffu, nb0 | nb1);
    if (lane == 0) outp[0] = bal;

#pragma unroll 2
    for (int ox = 1; ox <= 12; ox++) {
        C2_INT(2 * ox, nb0);
        C2_INT(2 * ox + 1, nb1);
        bal = __ballot_sync(0xffffffffu, nb0 | nb1);
        if (lane == 0) outp[2 * ox] = bal;
    }

    C2_INT(26, nb0);
    {   // X = 27 edge: taps dx in {0,1} read cols 26,27
        int a0 = __popc(tr[26] ^ wt[0]) + __popc(tr[27] ^ wt[1])
               + __popc(tr[54] ^ wt[3]) + __popc(tr[55] ^ wt[4])
               + __popc(tr[82] ^ wt[6]) + __popc(tr[83] ^ wt[7]);
        int a1 = __popc(tr[54] ^ wt[0]) + __popc(tr[55] ^ wt[1])
               + __popc(tr[82] ^ wt[3]) + __popc(tr[83] ^ wt[4])
               + __popc(tr[110] ^ wt[6]) + __popc(tr[111] ^ wt[7]);
        int d0 = Cr0 - 2 * a0, d1 = Cr1 - 2 * a1;
        nb1 = sgn ? (max(d0, d1) >= T) : (min(d0, d1) <= T);
    }
    bal = __ballot_sync(0xffffffffu, nb0 | nb1);
    if (lane == 0) outp[26] = bal;
#undef C2_INT
}

// ---------------- block2: warp/(img,row,half), lane = channel, CSA popc ----------------
__global__ void __launch_bounds__(256, 4) conv3_kernel() {
    __shared__ unsigned long long stile[4][4][14];     // 4 units x 4 input rows x 14 cols
    int tid = threadIdx.x;
    int U0 = blockIdx.x * 4;
    for (int i = tid; i < 224; i += 256) {
        int u = i / 56, r = i % 56, j = r / 14, col = r % 14;
        int U = U0 + u, b = U / 7, oy = U % 7;
        int ir = 2 * oy - 1 + j;
        stile[u][j][col] = (ir >= 0 && ir < 14) ? g_h2[b * 196 + ir * 14 + col] : 0ull;
    }
    __syncthreads();

    int w = tid >> 5, lane = tid & 31;
    int u = w >> 1, h = w & 1;
    int U = U0 + u, b = U / 7, oy = U % 7;
    int c = h * 32 + lane;

    unsigned long long wt[9];
#pragma unroll
    for (int t = 0; t < 9; t++) wt[t] = g_w3p[c * 10 + t];

    bool e0 = (oy == 0), e1 = (oy == 6);
    int v0 = e0 ? 2 : 3, v1 = e1 ? 2 : 3;
    int pw0 = __popcll(wt[0]), pw1 = __popcll(wt[1]), pw2 = __popcll(wt[2]);
    int pw6 = __popcll(wt[6]), pw7 = __popcll(wt[7]), pw8 = __popcll(wt[8]);
    int Ci0 = 192 * v0 + (e0 ? 2 * (pw0 + pw1 + pw2) : 0);
    int Ci1 = 192 * v1 + (e1 ? 2 * (pw6 + pw7 + pw8) : 0);
    int Cl0 = 128 * v0 + (e0 ? 2 * (pw1 + pw2) : 0);
    int Cl1 = 128 * v1 + (e1 ? 2 * (pw7 + pw8) : 0);
    int Cr0 = 128 * v0 + (e0 ? 2 * (pw0 + pw1) : 0);
    int Cr1 = 128 * v1 + (e1 ? 2 * (pw6 + pw7) : 0);

    int2 th = g_th3[c];
    int T = th.x;
    bool sgn = th.y != 0;
    const unsigned long long* tr = &stile[u][0][0];   // row stride 14
    uint32_t* outp = g_h3u + (b * 49 + oy * 7) * 2 + h;

#define C3_INT(X, nb) { \
    unsigned long long r0a = tr[(X)-1],    r0b = tr[(X)],    r0c = tr[(X)+1]; \
    unsigned long long r1a = tr[14+(X)-1], r1b = tr[14+(X)], r1c = tr[14+(X)+1]; \
    unsigned long long r2a = tr[28+(X)-1], r2b = tr[28+(X)], r2c = tr[28+(X)+1]; \
    unsigned long long r3a = tr[42+(X)-1], r3b = tr[42+(X)], r3c = tr[42+(X)+1]; \
    int a0, a1; \
    POP9_64(a0, r0a^wt[0], r0b^wt[1], r0c^wt[2], r1a^wt[3], r1b^wt[4], r1c^wt[5], \
                r2a^wt[6], r2b^wt[7], r2c^wt[8]); \
    POP9_64(a1, r1a^wt[0], r1b^wt[1], r1c^wt[2], r2a^wt[3], r2b^wt[4], r2c^wt[5], \
                r3a^wt[6], r3b^wt[7], r3c^wt[8]); \
    int d0 = Ci0 - 2 * a0, d1 = Ci1 - 2 * a1; \
    nb = sgn ? (max(d0, d1) >= T) : (min(d0, d1) <= T); }

    bool nb0, nb1;
    {   // X = 0 edge
        int a0 = __popcll(tr[0] ^ wt[1]) + __popcll(tr[1] ^ wt[2])
               + __popcll(tr[14] ^ wt[4]) + __popcll(tr[15] ^ wt[5])
               + __popcll(tr[28] ^ wt[7]) + __popcll(tr[29] ^ wt[8]);
        int a1 = __popcll(tr[14] ^ wt[1]) + __popcll(tr[15] ^ wt[2])
               + __popcll(tr[28] ^ wt[4]) + __popcll(tr[29] ^ wt[5])
               + __popcll(tr[42] ^ wt[7]) + __popcll(tr[43] ^ wt[8]);
        int d0 = Cl0 - 2 * a0, d1 = Cl1 - 2 * a1;
        nb0 = sgn ? (max(d0, d1) >= T) : (min(d0, d1) <= T);
    }
    C3_INT(1, nb1);
    uint32_t bal = __ballot_sync(0xffffffffu, nb0 | nb1);
    if (lane == 0) outp[0] = bal;

#pragma unroll 2
    for (int ox = 1; ox <= 5; ox++) {
        C3_INT(2 * ox, nb0);
        C3_INT(2 * ox + 1, nb1);
        bal = __ballot_sync(0xffffffffu, nb0 | nb1);
        if (lane == 0) outp[2 * ox] = bal;
    }

    C3_INT(12, nb0);
    {   // X = 13 edge
        int a0 = __popcll(tr[12] ^ wt[0]) + __popcll(tr[13] ^ wt[1])
               + __popcll(tr[26] ^ wt[3]) + __popcll(tr[27] ^ wt[4])
               + __popcll(tr[40] ^ wt[6]) + __popcll(tr[41] ^ wt[7]);
        int a1 = __popcll(tr[26] ^ wt[0]) + __popcll(tr[27] ^ wt[1])
               + __popcll(tr[40] ^ wt[3]) + __popcll(tr[41] ^ wt[4])
               + __popcll(tr[54] ^ wt[6]) + __popcll(tr[55] ^ wt[7]);
        int d0 = Cr0 - 2 * a0, d1 = Cr1 - 2 * a1;
        nb1 = sgn ? (max(d0, d1) >= T) : (min(d0, d1) <= T);
    }
    bal = __ballot_sync(0xffffffffu, nb0 | nb1);
    if (lane == 0) outp[12] = bal;
#undef C3_INT
}

// ---------------- classifier ----------------
__global__ void __launch_bounds__(256) fc_kernel(const float* __restrict__ w_head,
                                                 const float* __restrict__ b_head,
                                                 float* __restrict__ out) {
    __shared__ unsigned long long xrow[49];
    __shared__ float h4[256];
    int b = blockIdx.x, t = threadIdx.x;
    if (t < 49) {
        uint32_t lo = g_h3u[(b * 49 + t) * 2];
        uint32_t hi = g_h3u[(b * 49 + t) * 2 + 1];
        xrow[t] = (unsigned long long)lo | ((unsigned long long)hi << 32);
    }
    __syncthreads();

    const unsigned long long* wr = g_wfcp + t * 49;
    int acc = 0;
#pragma unroll
    for (int p = 0; p < 49; p++) acc += __popcll(xrow[p] ^ wr[p]);
    float4 bn = g_bn4[t];
    h4[t] = ((float)(3136 - 2 * acc) - bn.y) * bn.x + bn.z;
    __syncthreads();

    if (t < 10) {
        float s = b_head[t];
        const float* wh = w_head + t * 256;
#pragma unroll 8
        for (int c = 0; c < 256; c++) s += h4[c] * wh[c];
        out[b * 10 + t] = s;
    }
}

// ---------------- launch ----------------
extern "C" void kernel_launch(void* const* d_in, const int* in_sizes, int n_in,
                              void* d_out, int out_size) {
    const float* x      = (const float*)d_in[0];
    const float* w_stem = (const float*)d_in[1];
    const float* g1 = (const float*)d_in[2];
    const float* b1 = (const float*)d_in[3];
    const float* m1 = (const float*)d_in[4];
    const float* v1 = (const float*)d_in[5];
    const float* w2 = (const float*)d_in[6];
    const float* g2 = (const float*)d_in[7];
    const float* b2 = (const float*)d_in[8];
    const float* m2 = (const float*)d_in[9];
    const float* v2 = (const float*)d_in[10];
    const float* w3 = (const float*)d_in[11];
    const float* g3 = (const float*)d_in[12];
    const float* b3 = (const float*)d_in[13];
    const float* m3 = (const float*)d_in[14];
    const float* v3 = (const float*)d_in[15];
    const float* w_fc = (const float*)d_in[16];
    const float* g4 = (const float*)d_in[17];
    const float* b4 = (const float*)d_in[18];
    const float* m4 = (const float*)d_in[19];
    const float* v4 = (const float*)d_in[20];
    const float* w_head = (const float*)d_in[21];
    const float* b_head = (const float*)d_in[22];
    float* out = (float*)d_out;

    pack_kernel<<<57, 256>>>(w2, w3, w_fc, g1, v1, m1, b1, g2, v2, m2, b2,
                             g3, v3, m3, b3, g4, v4, m4, b4);
    stem_kernel<<<BATCH * 4, 224>>>(x, w_stem);      // 8192 blocks, 7 warps each
    conv2_kernel<<<(BATCH * 14) / 4, 256>>>();       // 7168 blocks
    conv3_kernel<<<(BATCH * 7) / 4, 256>>>();        // 3584 blocks
    fc_kernel<<<BATCH, 256>>>(w_head, b_head, out);
}

// round 15
// speedup vs baseline: 1.9249x; 1.0088x over previous
#include <cuda_runtime.h>
#include <stdint.h>

#define BATCH 2048
#define EPS 1e-5f

// ---------------- static scratch ----------------
__device__ uint32_t           g_h1[BATCH * 784];        // stem out, 32 ch packed
__device__ unsigned long long g_h2[BATCH * 196];        // block1 out, 64 ch packed (u32 halves)
__device__ uint32_t           g_h3u[BATCH * 49 * 2];    // block2 out, u32 halves
__device__ uint32_t           g_w2p[64 * 12];           // sign(w2), [ch][tap] stride 12
__device__ unsigned long long g_w3p[64 * 10];           // sign(w3), [ch][tap] stride 10
__device__ unsigned long long g_wfcp[256 * 49];         // sign(w_fc)
__device__ float4 g_bn4[256];                           // (inv, mean, beta, 0)
__device__ int2   g_th2[64], g_th3[64];                 // (integer threshold, sgn)

// IMAD helpers: force mad.lo.s32 so the adds dispatch to the (idle) FMA pipe
__device__ __forceinline__ int madi2(int a, int b) {
    int r; asm("mad.lo.s32 %0, %1, 2, %2;" : "=r"(r) : "r"(a), "r"(b)); return r;
}
__device__ __forceinline__ int madi4(int a, int b) {
    int r; asm("mad.lo.s32 %0, %1, 4, %2;" : "=r"(r) : "r"(a), "r"(b)); return r;
}
__device__ __forceinline__ int madin2(int a, int b) {
    int r; asm("mad.lo.s32 %0, %1, -2, %2;" : "=r"(r) : "r"(a), "r"(b)); return r;
}

// carry-save adder compressors (single LOP3 each after ptxas fusion)
#define CSA32(s, c, x, y, z) do { uint32_t _x = (x), _y = (y), _z = (z); \
    (s) = _x ^ _y ^ _z; (c) = (_x & _y) | (_z & (_x | _y)); } while (0)
#define CSA64(s, c, x, y, z) do { unsigned long long _x = (x), _y = (y), _z = (z); \
    (s) = _x ^ _y ^ _z; (c) = (_x & _y) | (_z & (_x | _y)); } while (0)

// popcount of sum of 9 words via full CSA tree: 4 POPC + IMAD chain
#define POP9_32(res, v0, v1, v2, v3, v4, v5, v6, v7, v8) do { \
    uint32_t _s1, _c1, _s2, _c2, _s3, _c3, _s4, _c4, _s5, _c5; \
    CSA32(_s1, _c1, v0, v1, v2); CSA32(_s2, _c2, v3, v4, v5); CSA32(_s3, _c3, v6, v7, v8); \
    CSA32(_s4, _c4, _s1, _s2, _s3); CSA32(_s5, _c5, _c1, _c2, _c3); \
    (res) = madi2(__popc(_c4), madi2(__popc(_s5), madi4(__popc(_c5), __popc(_s4)))); } while (0)
#define POP9_64(res, v0, v1, v2, v3, v4, v5, v6, v7, v8) do { \
    unsigned long long _s1, _c1, _s2, _c2, _s3, _c3, _s4, _c4, _s5, _c5; \
    CSA64(_s1, _c1, v0, v1, v2); CSA64(_s2, _c2, v3, v4, v5); CSA64(_s3, _c3, v6, v7, v8); \
    CSA64(_s4, _c4, _s1, _s2, _s3); CSA64(_s5, _c5, _c1, _c2, _c3); \
    (res) = madi2(__popcll(_c4), madi2(__popcll(_s5), madi4(__popcll(_c5), __popcll(_s4)))); } while (0)

// ---------------- stem (warp per row, lane = channel) + merged pack ----------------
// blocks [0, BATCH*4): stem; blocks [BATCH*4, BATCH*4+65): packing/threshold work
__global__ void __launch_bounds__(224) stem_pack_kernel(
        const float* __restrict__ x, const float* __restrict__ ws,
        const float* __restrict__ w2, const float* __restrict__ w3,
        const float* __restrict__ wfc,
        const float* __restrict__ g1, const float* __restrict__ v1,
        const float* __restrict__ m1, const float* __restrict__ b1,
        const float* __restrict__ g2, const float* __restrict__ v2,
        const float* __restrict__ m2, const float* __restrict__ b2,
        const float* __restrict__ g3, const float* __restrict__ v3,
        const float* __restrict__ m3, const float* __restrict__ b3,
        const float* __restrict__ g4, const float* __restrict__ v4,
        const float* __restrict__ m4, const float* __restrict__ b4) {
    int tid = threadIdx.x;

    if (blockIdx.x >= BATCH * 4) {                     // ---- pack branch ----
        int idx = (blockIdx.x - BATCH * 4) * 224 + tid;
        if (idx < 768) {                               // w2: [64,32,3,3] -> stride 12
            int o = idx / 12, t = idx % 12;
            uint32_t bits = 0;
            if (t < 9)
                for (int c = 0; c < 32; c++)
                    bits |= (w2[o * 288 + c * 9 + t] >= 0.f ? 1u : 0u) << c;
            g_w2p[idx] = bits;
        } else if (idx < 1408) {                       // w3: [64,64,3,3] -> stride 10
            int j = idx - 768; int o = j / 10, t = j % 10;
            unsigned long long bits = 0;
            if (t < 9)
                for (int c = 0; c < 64; c++)
                    bits |= (unsigned long long)(w3[o * 576 + c * 9 + t] >= 0.f) << c;
            g_w3p[j] = bits;
        } else if (idx < 13952) {                      // w_fc: [256,3136]
            int j = idx - 1408; int o = j / 49, p = j % 49;
            unsigned long long bits = 0;
            for (int c = 0; c < 64; c++)
                bits |= (unsigned long long)(wfc[o * 3136 + c * 49 + p] >= 0.f) << c;
            g_wfcp[j] = bits;
        } else if (idx < 14208) {
            int c = idx - 13952;
            g_bn4[c] = make_float4(g4[c] / sqrtf(v4[c] + EPS), m4[c], b4[c], 0.f);
        } else if (idx < 14272) {                      // conv2 thresholds
            int c = idx - 14208;
            float inv = g2[c] / sqrtf(v2[c] + EPS), m = m2[c], be = b2[c];
            int sgn = (inv >= 0.f) ? 1 : 0;
            int T;
            if (sgn) {
                T = 10000;
                for (int d = -288; d <= 288; d += 2)
                    if (((float)d - m) * inv + be >= 0.f) { T = d; break; }
            } else {
                T = -10000;
                for (int d = 288; d >= -288; d -= 2)
                    if (((float)d - m) * inv + be >= 0.f) { T = d; break; }
            }
            g_th2[c] = make_int2(T, sgn);
        } else if (idx < 14336) {                      // conv3 thresholds
            int c = idx - 14272;
            float inv = g3[c] / sqrtf(v3[c] + EPS), m = m3[c], be = b3[c];
            int sgn = (inv >= 0.f) ? 1 : 0;
            int T;
            if (sgn) {
                T = 10000;
                for (int d = -576; d <= 576; d += 2)
                    if (((float)d - m) * inv + be >= 0.f) { T = d; break; }
            } else {
                T = -10000;
                for (int d = 576; d >= -576; d -= 2)
                    if (((float)d - m) * inv + be >= 0.f) { T = d; break; }
            }
            g_th3[c] = make_int2(T, sgn);
        }
        return;
    }

    // ---- stem branch ----
    __shared__ float tile[9][32];                      // rows y0-1..y0+7, cols x=-1..28
    int img = blockIdx.x >> 2, q = blockIdx.x & 3;
    int y0 = q * 7;
    const float* xb = x + img * 784;

    for (int i = tid; i < 270; i += 224) {
        int r = i / 30, col = i % 30;
        int yy = y0 - 1 + r, xc = col - 1;
        float v = 0.f;
        if (yy >= 0 && yy < 28 && xc >= 0 && xc < 28) v = xb[yy * 28 + xc];
        tile[r][col] = v;
    }

    int wid = tid >> 5, lane = tid & 31;
    float wt[9];
#pragma unroll
    for (int k = 0; k < 9; k++) wt[k] = ws[lane * 9 + k];
    float bnx = g1[lane] / sqrtf(v1[lane] + EPS);      // same expression as pack used
    float bny = m1[lane], bnz = b1[lane];
    __syncthreads();

    int y = y0 + wid;
    uint32_t* orow = g_h1 + img * 784 + y * 28;

    // sliding 3-column window (renamed regs: p=left, q=mid, r=right)
    float p0 = tile[wid][0],     p1 = tile[wid + 1][0],     p2 = tile[wid + 2][0];
    float q0 = tile[wid][1],     q1 = tile[wid + 1][1],     q2 = tile[wid + 2][1];

#pragma unroll
    for (int xx = 0; xx < 28; xx++) {
        float r0 = tile[wid][xx + 2], r1 = tile[wid + 1][xx + 2], r2 = tile[wid + 2][xx + 2];
        // accumulation order identical to previous passing version: k = 0..8
        float s = wt[0] * p0;
        s += wt[1] * q0;  s += wt[2] * r0;
        s += wt[3] * p1;  s += wt[4] * q1;  s += wt[5] * r1;
        s += wt[6] * p2;  s += wt[7] * q2;  s += wt[8] * r2;
        float v = (s - bny) * bnx + bnz;
        uint32_t bits = __ballot_sync(0xffffffffu, v >= 0.f);
        if (lane == 0) orow[xx] = bits;
        p0 = q0; p1 = q1; p2 = q2;
        q0 = r0; q1 = r1; q2 = r2;
    }
}

// ---------------- block1: warp/(img,row,half), lane = channel, CSA popc ----------------
__global__ void __launch_bounds__(256, 4) conv2_kernel() {
    __shared__ uint32_t stile[4][4][28];               // 4 units x 4 input rows x 28 cols
    int tid = threadIdx.x;
    int U0 = blockIdx.x * 4;
    for (int i = tid; i < 448; i += 256) {
        int u = i / 112, r = i % 112, j = r / 28, col = r % 28;
        int U = U0 + u, b = U / 14, oy = U % 14;
        int ir = 2 * oy - 1 + j;
        stile[u][j][col] = (ir >= 0 && ir < 28) ? g_h1[b * 784 + ir * 28 + col] : 0u;
    }
    __syncthreads();

    int w = tid >> 5, lane = tid & 31;
    int u = w >> 1, h = w & 1;
    int U = U0 + u, b = U / 14, oy = U % 14;
    int c = h * 32 + lane;

    uint32_t wt[9];
#pragma unroll
    for (int t = 0; t < 9; t++) wt[t] = g_w2p[c * 12 + t];

    bool e0 = (oy == 0), e1 = (oy == 13);
    int v0 = e0 ? 2 : 3, v1 = e1 ? 2 : 3;
    int pw0 = __popc(wt[0]), pw1 = __popc(wt[1]), pw2 = __popc(wt[2]);
    int pw6 = __popc(wt[6]), pw7 = __popc(wt[7]), pw8 = __popc(wt[8]);
    int Ci0 = 96 * v0 + (e0 ? 2 * (pw0 + pw1 + pw2) : 0);
    int Ci1 = 96 * v1 + (e1 ? 2 * (pw6 + pw7 + pw8) : 0);
    int Cl0 = 64 * v0 + (e0 ? 2 * (pw1 + pw2) : 0);    // X=0 edge (dx in {1,2})
    int Cl1 = 64 * v1 + (e1 ? 2 * (pw7 + pw8) : 0);
    int Cr0 = 64 * v0 + (e0 ? 2 * (pw0 + pw1) : 0);    // X=27 edge (dx in {0,1})
    int Cr1 = 64 * v1 + (e1 ? 2 * (pw6 + pw7) : 0);

    int2 th = g_th2[c];
    int T = th.x;
    bool sgn = th.y != 0;
    const uint32_t* tr = &stile[u][0][0];
    uint32_t* outp = ((uint32_t*)g_h2) + (b * 196 + oy * 14) * 2 + h;

#define C2_INT(X, nb) { \
    uint32_t r0a = tr[(X)-1],    r0b = tr[(X)],    r0c = tr[(X)+1]; \
    uint32_t r1a = tr[28+(X)-1], r1b = tr[28+(X)], r1c = tr[28+(X)+1]; \
    uint32_t r2a = tr[56+(X)-1], r2b = tr[56+(X)], r2c = tr[56+(X)+1]; \
    uint32_t r3a = tr[84+(X)-1], r3b = tr[84+(X)], r3c = tr[84+(X)+1]; \
    int a0, a1; \
    POP9_32(a0, r0a^wt[0], r0b^wt[1], r0c^wt[2], r1a^wt[3], r1b^wt[4], r1c^wt[5], \
                r2a^wt[6], r2b^wt[7], r2c^wt[8]); \
    POP9_32(a1, r1a^wt[0], r1b^wt[1], r1c^wt[2], r2a^wt[3], r2b^wt[4], r2c^wt[5], \
                r3a^wt[6], r3b^wt[7], r3c^wt[8]); \
    int d0 = madin2(a0, Ci0), d1 = madin2(a1, Ci1); \
    nb = sgn ? (max(d0, d1) >= T) : (min(d0, d1) <= T); }

    bool nb0, nb1;
    {   // X = 0 edge: taps dx in {1,2} read cols 0,1
        int a0 = __popc(tr[0] ^ wt[1]) + __popc(tr[1] ^ wt[2])
               + __popc(tr[28] ^ wt[4]) + __popc(tr[29] ^ wt[5])
               + __popc(tr[56] ^ wt[7]) + __popc(tr[57] ^ wt[8]);
        int a1 = __popc(tr[28] ^ wt[1]) + __popc(tr[29] ^ wt[2])
               + __popc(tr[56] ^ wt[4]) + __popc(tr[57] ^ wt[5])
               + __popc(tr[84] ^ wt[7]) + __popc(tr[85] ^ wt[8]);
        int d0 = madin2(a0, Cl0), d1 = madin2(a1, Cl1);
        nb0 = sgn ? (max(d0, d1) >= T) : (min(d0, d1) <= T);
    }
    C2_INT(1, nb1);
    uint32_t bal = __ballot_sync(0xffffffffu, nb0 | nb1);
    if (lane == 0) outp[0] = bal;

#pragma unroll 2
    for (int ox = 1; ox <= 12; ox++) {
        C2_INT(2 * ox, nb0);
        C2_INT(2 * ox + 1, nb1);
        bal = __ballot_sync(0xffffffffu, nb0 | nb1);
        if (lane == 0) outp[2 * ox] = bal;
    }

    C2_INT(26, nb0);
    {   // X = 27 edge: taps dx in {0,1} read cols 26,27
        int a0 = __popc(tr[26] ^ wt[0]) + __popc(tr[27] ^ wt[1])
               + __popc(tr[54] ^ wt[3]) + __popc(tr[55] ^ wt[4])
               + __popc(tr[82] ^ wt[6]) + __popc(tr[83] ^ wt[7]);
        int a1 = __popc(tr[54] ^ wt[0]) + __popc(tr[55] ^ wt[1])
               + __popc(tr[82] ^ wt[3]) + __popc(tr[83] ^ wt[4])
               + __popc(tr[110] ^ wt[6]) + __popc(tr[111] ^ wt[7]);
        int d0 = madin2(a0, Cr0), d1 = madin2(a1, Cr1);
        nb1 = sgn ? (max(d0, d1) >= T) : (min(d0, d1) <= T);
    }
    bal = __ballot_sync(0xffffffffu, nb0 | nb1);
    if (lane == 0) outp[26] = bal;
#undef C2_INT
}

// ---------------- block2: warp/(img,row,half), lane = channel, CSA popc ----------------
__global__ void __launch_bounds__(256, 4) conv3_kernel() {
    __shared__ unsigned long long stile[4][4][14];     // 4 units x 4 input rows x 14 cols
    int tid = threadIdx.x;
    int U0 = blockIdx.x * 4;
    for (int i = tid; i < 224; i += 256) {
        int u = i / 56, r = i % 56, j = r / 14, col = r % 14;
        int U = U0 + u, b = U / 7, oy = U % 7;
        int ir = 2 * oy - 1 + j;
        stile[u][j][col] = (ir >= 0 && ir < 14) ? g_h2[b * 196 + ir * 14 + col] : 0ull;
    }
    __syncthreads();

    int w = tid >> 5, lane = tid & 31;
    int u = w >> 1, h = w & 1;
    int U = U0 + u, b = U / 7, oy = U % 7;
    int c = h * 32 + lane;

    unsigned long long wt[9];
#pragma unroll
    for (int t = 0; t < 9; t++) wt[t] = g_w3p[c * 10 + t];

    bool e0 = (oy == 0), e1 = (oy == 6);
    int v0 = e0 ? 2 : 3, v1 = e1 ? 2 : 3;
    int pw0 = __popcll(wt[0]), pw1 = __popcll(wt[1]), pw2 = __popcll(wt[2]);
    int pw6 = __popcll(wt[6]), pw7 = __popcll(wt[7]), pw8 = __popcll(wt[8]);
    int Ci0 = 192 * v0 + (e0 ? 2 * (pw0 + pw1 + pw2) : 0);
    int Ci1 = 192 * v1 + (e1 ? 2 * (pw6 + pw7 + pw8) : 0);
    int Cl0 = 128 * v0 + (e0 ? 2 * (pw1 + pw2) : 0);
    int Cl1 = 128 * v1 + (e1 ? 2 * (pw7 + pw8) : 0);
    int Cr0 = 128 * v0 + (e0 ? 2 * (pw0 + pw1) : 0);
    int Cr1 = 128 * v1 + (e1 ? 2 * (pw6 + pw7) : 0);

    int2 th = g_th3[c];
    int T = th.x;
    bool sgn = th.y != 0;
    const unsigned long long* tr = &stile[u][0][0];   // row stride 14
    uint32_t* outp = g_h3u + (b * 49 + oy * 7) * 2 + h;

#define C3_INT(X, nb) { \
    unsigned long long r0a = tr[(X)-1],    r0b = tr[(X)],    r0c = tr[(X)+1]; \
    unsigned long long r1a = tr[14+(X)-1], r1b = tr[14+(X)], r1c = tr[14+(X)+1]; \
    unsigned long long r2a = tr[28+(X)-1], r2b = tr[28+(X)], r2c = tr[28+(X)+1]; \
    unsigned long long r3a = tr[42+(X)-1], r3b = tr[42+(X)], r3c = tr[42+(X)+1]; \
    int a0, a1; \
    POP9_64(a0, r0a^wt[0], r0b^wt[1], r0c^wt[2], r1a^wt[3], r1b^wt[4], r1c^wt[5], \
                r2a^wt[6], r2b^wt[7], r2c^wt[8]); \
    POP9_64(a1, r1a^wt[0], r1b^wt[1], r1c^wt[2], r2a^wt[3], r2b^wt[4], r2c^wt[5], \
                r3a^wt[6], r3b^wt[7], r3c^wt[8]); \
    int d0 = madin2(a0, Ci0), d1 = madin2(a1, Ci1); \
    nb = sgn ? (max(d0, d1) >= T) : (min(d0, d1) <= T); }

    bool nb0, nb1;
    {   // X = 0 edge
        int a0 = __popcll(tr[0] ^ wt[1]) + __popcll(tr[1] ^ wt[2])
               + __popcll(tr[14] ^ wt[4]) + __popcll(tr[15] ^ wt[5])
               + __popcll(tr[28] ^ wt[7]) + __popcll(tr[29] ^ wt[8]);
        int a1 = __popcll(tr[14] ^ wt[1]) + __popcll(tr[15] ^ wt[2])
               + __popcll(tr[28] ^ wt[4]) + __popcll(tr[29] ^ wt[5])
               + __popcll(tr[42] ^ wt[7]) + __popcll(tr[43] ^ wt[8]);
        int d0 = madin2(a0, Cl0), d1 = madin2(a1, Cl1);
        nb0 = sgn ? (max(d0, d1) >= T) : (min(d0, d1) <= T);
    }
    C3_INT(1, nb1);
    uint32_t bal = __ballot_sync(0xffffffffu, nb0 | nb1);
    if (lane == 0) outp[0] = bal;

#pragma unroll 2
    for (int ox = 1; ox <= 5; ox++) {
        C3_INT(2 * ox, nb0);
        C3_INT(2 * ox + 1, nb1);
        bal = __ballot_sync(0xffffffffu, nb0 | nb1);
        if (lane == 0) outp[2 * ox] = bal;
    }

    C3_INT(12, nb0);
    {   // X = 13 edge
        int a0 = __popcll(tr[12] ^ wt[0]) + __popcll(tr[13] ^ wt[1])
               + __popcll(tr[26] ^ wt[3]) + __popcll(tr[27] ^ wt[4])
               + __popcll(tr[40] ^ wt[6]) + __popcll(tr[41] ^ wt[7]);
        int a1 = __popcll(tr[26] ^ wt[0]) + __popcll(tr[27] ^ wt[1])
               + __popcll(tr[40] ^ wt[3]) + __popcll(tr[41] ^ wt[4])
               + __popcll(tr[54] ^ wt[6]) + __popcll(tr[55] ^ wt[7]);
        int d0 = madin2(a0, Cr0), d1 = madin2(a1, Cr1);
        nb1 = sgn ? (max(d0, d1) >= T) : (min(d0, d1) <= T);
    }
    bal = __ballot_sync(0xffffffffu, nb0 | nb1);
    if (lane == 0) outp[12] = bal;
#undef C3_INT
}

// ---------------- classifier ----------------
__global__ void __launch_bounds__(256) fc_kernel(const float* __restrict__ w_head,
                                                 const float* __restrict__ b_head,
                                                 float* __restrict__ out) {
    __shared__ unsigned long long xrow[49];
    __shared__ float h4[256];
    int b = blockIdx.x, t = threadIdx.x;
    if (t < 49) {
        uint32_t lo = g_h3u[(b * 49 + t) * 2];
        uint32_t hi = g_h3u[(b * 49 + t) * 2 + 1];
        xrow[t] = (unsigned long long)lo | ((unsigned long long)hi << 32);
    }
    __syncthreads();

    const unsigned long long* wr = g_wfcp + t * 49;
    int acc = 0;
#pragma unroll
    for (int p = 0; p < 49; p++) acc += __popcll(xrow[p] ^ wr[p]);
    float4 bn = g_bn4[t];
    h4[t] = ((float)(3136 - 2 * acc) - bn.y) * bn.x + bn.z;
    __syncthreads();

    if (t < 10) {
        float s = b_head[t];
        const float* wh = w_head + t * 256;
#pragma unroll 8
        for (int c = 0; c < 256; c++) s += h4[c] * wh[c];
        out[b * 10 + t] = s;
    }
}

// ---------------- launch ----------------
extern "C" void kernel_launch(void* const* d_in, const int* in_sizes, int n_in,
                              void* d_out, int out_size) {
    const float* x      = (const float*)d_in[0];
    const float* w_stem = (const float*)d_in[1];
    const float* g1 = (const float*)d_in[2];
    const float* b1 = (const float*)d_in[3];
    const float* m1 = (const float*)d_in[4];
    const float* v1 = (const float*)d_in[5];
    const float* w2 = (const float*)d_in[6];
    const float* g2 = (const float*)d_in[7];
    const float* b2 = (const float*)d_in[8];
    const float* m2 = (const float*)d_in[9];
    const float* v2 = (const float*)d_in[10];
    const float* w3 = (const float*)d_in[11];
    const float* g3 = (const float*)d_in[12];
    const float* b3 = (const float*)d_in[13];
    const float* m3 = (const float*)d_in[14];
    const float* v3 = (const float*)d_in[15];
    const float* w_fc = (const float*)d_in[16];
    const float* g4 = (const float*)d_in[17];
    const float* b4 = (const float*)d_in[18];
    const float* m4 = (const float*)d_in[19];
    const float* v4 = (const float*)d_in[20];
    const float* w_head = (const float*)d_in[21];
    const float* b_head = (const float*)d_in[22];
    float* out = (float*)d_out;

    stem_pack_kernel<<<BATCH * 4 + 65, 224>>>(x, w_stem, w2, w3, w_fc,
                                              g1, v1, m1, b1, g2, v2, m2, b2,
                                              g3, v3, m3, b3, g4, v4, m4, b4);
    conv2_kernel<<<(BATCH * 14) / 4, 256>>>();       // 7168 blocks
    conv3_kernel<<<(BATCH * 7) / 4, 256>>>();        // 3584 blocks
    fc_kernel<<<BATCH, 256>>>(w_head, b_head, out);
}

// round 16
// speedup vs baseline: 1.9810x; 1.0291x over previous
#include <cuda_runtime.h>
#include <stdint.h>

#define BATCH 2048
#define EPS 1e-5f
#define FC_IMGS 13
#define FC_BLOCKS ((BATCH + FC_IMGS - 1) / FC_IMGS)

// ---------------- static scratch ----------------
__device__ uint32_t           g_h1[BATCH * 784];        // stem out, 32 ch packed
__device__ unsigned long long g_h2[BATCH * 196];        // block1 out, 64 ch packed (u32 halves)
__device__ uint32_t           g_h3u[BATCH * 49 * 2];    // block2 out, u32 halves
__device__ uint32_t           g_w2p[64 * 12];           // sign(w2), [ch][tap] stride 12
__device__ unsigned long long g_w3p[64 * 10];           // sign(w3), [ch][tap] stride 10
__device__ unsigned long long g_wfcp[256 * 49];         // sign(w_fc)
__device__ float4 g_bn4[256];                           // (inv, mean, beta, 0)
__device__ int2   g_th2[64], g_th3[64];                 // (integer threshold, sgn)

// IMAD helpers: force mad.lo.s32 so the adds dispatch to the FMA pipe
__device__ __forceinline__ int madi2(int a, int b) {
    int r; asm("mad.lo.s32 %0, %1, 2, %2;" : "=r"(r) : "r"(a), "r"(b)); return r;
}
__device__ __forceinline__ int madi4(int a, int b) {
    int r; asm("mad.lo.s32 %0, %1, 4, %2;" : "=r"(r) : "r"(a), "r"(b)); return r;
}
__device__ __forceinline__ int madin2(int a, int b) {
    int r; asm("mad.lo.s32 %0, %1, -2, %2;" : "=r"(r) : "r"(a), "r"(b)); return r;
}

// carry-save adder compressors (single LOP3 each after ptxas fusion)
#define CSA32(s, c, x, y, z) do { uint32_t _x = (x), _y = (y), _z = (z); \
    (s) = _x ^ _y ^ _z; (c) = (_x & _y) | (_z & (_x | _y)); } while (0)
#define CSA64(s, c, x, y, z) do { unsigned long long _x = (x), _y = (y), _z = (z); \
    (s) = _x ^ _y ^ _z; (c) = (_x & _y) | (_z & (_x | _y)); } while (0)

// popcount of sum of 9 words via full CSA tree: 4 POPC + IMAD chain
#define POP9_32(res, v0, v1, v2, v3, v4, v5, v6, v7, v8) do { \
    uint32_t _s1, _c1, _s2, _c2, _s3, _c3, _s4, _c4, _s5, _c5; \
    CSA32(_s1, _c1, v0, v1, v2); CSA32(_s2, _c2, v3, v4, v5); CSA32(_s3, _c3, v6, v7, v8); \
    CSA32(_s4, _c4, _s1, _s2, _s3); CSA32(_s5, _c5, _c1, _c2, _c3); \
    (res) = madi2(__popc(_c4), madi2(__popc(_s5), madi4(__popc(_c5), __popc(_s4)))); } while (0)
#define POP9_64(res, v0, v1, v2, v3, v4, v5, v6, v7, v8) do { \
    unsigned long long _s1, _c1, _s2, _c2, _s3, _c3, _s4, _c4, _s5, _c5; \
    CSA64(_s1, _c1, v0, v1, v2); CSA64(_s2, _c2, v3, v4, v5); CSA64(_s3, _c3, v6, v7, v8); \
    CSA64(_s4, _c4, _s1, _s2, _s3); CSA64(_s5, _c5, _c1, _c2, _c3); \
    (res) = madi2(__popcll(_c4), madi2(__popcll(_s5), madi4(__popcll(_c5), __popcll(_s4)))); } while (0)

// ---------------- stem (warp per row, lane = channel) + merged pack ----------------
__global__ void __launch_bounds__(224) stem_pack_kernel(
        const float* __restrict__ x, const float* __restrict__ ws,
        const float* __restrict__ w2, const float* __restrict__ w3,
        const float* __restrict__ wfc,
        const float* __restrict__ g1, const float* __restrict__ v1,
        const float* __restrict__ m1, const float* __restrict__ b1,
        const float* __restrict__ g2, const float* __restrict__ v2,
        const float* __restrict__ m2, const float* __restrict__ b2,
        const float* __restrict__ g3, const float* __restrict__ v3,
        const float* __restrict__ m3, const float* __restrict__ b3,
        const float* __restrict__ g4, const float* __restrict__ v4,
        const float* __restrict__ m4, const float* __restrict__ b4) {
    int tid = threadIdx.x;

    if (blockIdx.x >= BATCH * 4) {                     // ---- pack branch ----
        int idx = (blockIdx.x - BATCH * 4) * 224 + tid;
        if (idx < 768) {                               // w2: [64,32,3,3] -> stride 12
            int o = idx / 12, t = idx % 12;
            uint32_t bits = 0;
            if (t < 9)
                for (int c = 0; c < 32; c++)
                    bits |= (w2[o * 288 + c * 9 + t] >= 0.f ? 1u : 0u) << c;
            g_w2p[idx] = bits;
        } else if (idx < 1408) {                       // w3: [64,64,3,3] -> stride 10
            int j = idx - 768; int o = j / 10, t = j % 10;
            unsigned long long bits = 0;
            if (t < 9)
                for (int c = 0; c < 64; c++)
                    bits |= (unsigned long long)(w3[o * 576 + c * 9 + t] >= 0.f) << c;
            g_w3p[j] = bits;
        } else if (idx < 13952) {                      // w_fc: [256,3136]
            int j = idx - 1408; int o = j / 49, p = j % 49;
            unsigned long long bits = 0;
            for (int c = 0; c < 64; c++)
                bits |= (unsigned long long)(wfc[o * 3136 + c * 49 + p] >= 0.f) << c;
            g_wfcp[j] = bits;
        } else if (idx < 14208) {
            int c = idx - 13952;
            g_bn4[c] = make_float4(g4[c] / sqrtf(v4[c] + EPS), m4[c], b4[c], 0.f);
        } else if (idx < 14272) {                      // conv2 thresholds
            int c = idx - 14208;
            float inv = g2[c] / sqrtf(v2[c] + EPS), m = m2[c], be = b2[c];
            int sgn = (inv >= 0.f) ? 1 : 0;
            int T;
            if (sgn) {
                T = 10000;
                for (int d = -288; d <= 288; d += 2)
                    if (((float)d - m) * inv + be >= 0.f) { T = d; break; }
            } else {
                T = -10000;
                for (int d = 288; d >= -288; d -= 2)
                    if (((float)d - m) * inv + be >= 0.f) { T = d; break; }
            }
            g_th2[c] = make_int2(T, sgn);
        } else if (idx < 14336) {                      // conv3 thresholds
            int c = idx - 14272;
            float inv = g3[c] / sqrtf(v3[c] + EPS), m = m3[c], be = b3[c];
            int sgn = (inv >= 0.f) ? 1 : 0;
            int T;
            if (sgn) {
                T = 10000;
                for (int d = -576; d <= 576; d += 2)
                    if (((float)d - m) * inv + be >= 0.f) { T = d; break; }
            } else {
                T = -10000;
                for (int d = 576; d >= -576; d -= 2)
                    if (((float)d - m) * inv + be >= 0.f) { T = d; break; }
            }
            g_th3[c] = make_int2(T, sgn);
        }
        return;
    }

    // ---- stem branch ----
    __shared__ float tile[9][32];
    int img = blockIdx.x >> 2, q = blockIdx.x & 3;
    int y0 = q * 7;
    const float* xb = x + img * 784;

    for (int i = tid; i < 270; i += 224) {
        int r = i / 30, col = i % 30;
        int yy = y0 - 1 + r, xc = col - 1;
        float v = 0.f;
        if (yy >= 0 && yy < 28 && xc >= 0 && xc < 28) v = xb[yy * 28 + xc];
        tile[r][col] = v;
    }

    int wid = tid >> 5, lane = tid & 31;
    float wt[9];
#pragma unroll
    for (int k = 0; k < 9; k++) wt[k] = ws[lane * 9 + k];
    float bnx = g1[lane] / sqrtf(v1[lane] + EPS);
    float bny = m1[lane], bnz = b1[lane];
    __syncthreads();

    int y = y0 + wid;
    uint32_t* orow = g_h1 + img * 784 + y * 28;

    float p0 = tile[wid][0],     p1 = tile[wid + 1][0],     p2 = tile[wid + 2][0];
    float q0 = tile[wid][1],     q1 = tile[wid + 1][1],     q2 = tile[wid + 2][1];

#pragma unroll
    for (int xx = 0; xx < 28; xx++) {
        float r0 = tile[wid][xx + 2], r1 = tile[wid + 1][xx + 2], r2 = tile[wid + 2][xx + 2];
        float s = wt[0] * p0;
        s += wt[1] * q0;  s += wt[2] * r0;
        s += wt[3] * p1;  s += wt[4] * q1;  s += wt[5] * r1;
        s += wt[6] * p2;  s += wt[7] * q2;  s += wt[8] * r2;
        float v = (s - bny) * bnx + bnz;
        uint32_t bits = __ballot_sync(0xffffffffu, v >= 0.f);
        if (lane == 0) orow[xx] = bits;
        p0 = q0; p1 = q1; p2 = q2;
        q0 = r0; q1 = r1; q2 = r2;
    }
}

// ---------------- block1: warp/(img,row,half), lane = channel, CSA popc ----------------
__global__ void __launch_bounds__(256, 4) conv2_kernel() {
    __shared__ uint32_t stile[4][4][28];
    int tid = threadIdx.x;
    int U0 = blockIdx.x * 4;
    for (int i = tid; i < 448; i += 256) {
        int u = i / 112, r = i % 112, j = r / 28, col = r % 28;
        int U = U0 + u, b = U / 14, oy = U % 14;
        int ir = 2 * oy - 1 + j;
        stile[u][j][col] = (ir >= 0 && ir < 28) ? g_h1[b * 784 + ir * 28 + col] : 0u;
    }
    __syncthreads();

    int w = tid >> 5, lane = tid & 31;
    int u = w >> 1, h = w & 1;
    int U = U0 + u, b = U / 14, oy = U % 14;
    int c = h * 32 + lane;

    uint32_t wt[9];
#pragma unroll
    for (int t = 0; t < 9; t++) wt[t] = g_w2p[c * 12 + t];

    bool e0 = (oy == 0), e1 = (oy == 13);
    int v0 = e0 ? 2 : 3, v1 = e1 ? 2 : 3;
    int pw0 = __popc(wt[0]), pw1 = __popc(wt[1]), pw2 = __popc(wt[2]);
    int pw6 = __popc(wt[6]), pw7 = __popc(wt[7]), pw8 = __popc(wt[8]);
    int Ci0 = 96 * v0 + (e0 ? 2 * (pw0 + pw1 + pw2) : 0);
    int Ci1 = 96 * v1 + (e1 ? 2 * (pw6 + pw7 + pw8) : 0);
    int Cl0 = 64 * v0 + (e0 ? 2 * (pw1 + pw2) : 0);
    int Cl1 = 64 * v1 + (e1 ? 2 * (pw7 + pw8) : 0);
    int Cr0 = 64 * v0 + (e0 ? 2 * (pw0 + pw1) : 0);
    int Cr1 = 64 * v1 + (e1 ? 2 * (pw6 + pw7) : 0);

    int2 th = g_th2[c];
    int T = th.x;
    bool sgn = th.y != 0;
    const uint32_t* tr = &stile[u][0][0];
    uint32_t* outp = ((uint32_t*)g_h2) + (b * 196 + oy * 14) * 2 + h;

#define C2_INT(X, nb) { \
    uint32_t r0a = tr[(X)-1],    r0b = tr[(X)],    r0c = tr[(X)+1]; \
    uint32_t r1a = tr[28+(X)-1], r1b = tr[28+(X)], r1c = tr[28+(X)+1]; \
    uint32_t r2a = tr[56+(X)-1], r2b = tr[56+(X)], r2c = tr[56+(X)+1]; \
    uint32_t r3a = tr[84+(X)-1], r3b = tr[84+(X)], r3c = tr[84+(X)+1]; \
    int a0, a1; \
    POP9_32(a0, r0a^wt[0], r0b^wt[1], r0c^wt[2], r1a^wt[3], r1b^wt[4], r1c^wt[5], \
                r2a^wt[6], r2b^wt[7], r2c^wt[8]); \
    POP9_32(a1, r1a^wt[0], r1b^wt[1], r1c^wt[2], r2a^wt[3], r2b^wt[4], r2c^wt[5], \
                r3a^wt[6], r3b^wt[7], r3c^wt[8]); \
    int d0 = madin2(a0, Ci0), d1 = madin2(a1, Ci1); \
    nb = sgn ? (max(d0, d1) >= T) : (min(d0, d1) <= T); }

    bool nb0, nb1;
    {   // X = 0 edge
        int a0 = __popc(tr[0] ^ wt[1]) + __popc(tr[1] ^ wt[2])
               + __popc(tr[28] ^ wt[4]) + __popc(tr[29] ^ wt[5])
               + __popc(tr[56] ^ wt[7]) + __popc(tr[57] ^ wt[8]);
        int a1 = __popc(tr[28] ^ wt[1]) + __popc(tr[29] ^ wt[2])
               + __popc(tr[56] ^ wt[4]) + __popc(tr[57] ^ wt[5])
               + __popc(tr[84] ^ wt[7]) + __popc(tr[85] ^ wt[8]);
        int d0 = madin2(a0, Cl0), d1 = madin2(a1, Cl1);
        nb0 = sgn ? (max(d0, d1) >= T) : (min(d0, d1) <= T);
    }
    C2_INT(1, nb1);
    uint32_t bal = __ballot_sync(0xffffffffu, nb0 | nb1);
    if (lane == 0) outp[0] = bal;

#pragma unroll 2
    for (int ox = 1; ox <= 12; ox++) {
        C2_INT(2 * ox, nb0);
        C2_INT(2 * ox + 1, nb1);
        bal = __ballot_sync(0xffffffffu, nb0 | nb1);
        if (lane == 0) outp[2 * ox] = bal;
    }

    C2_INT(26, nb0);
    {   // X = 27 edge
        int a0 = __popc(tr[26] ^ wt[0]) + __popc(tr[27] ^ wt[1])
               + __popc(tr[54] ^ wt[3]) + __popc(tr[55] ^ wt[4])
               + __popc(tr[82] ^ wt[6]) + __popc(tr[83] ^ wt[7]);
        int a1 = __popc(tr[54] ^ wt[0]) + __popc(tr[55] ^ wt[1])
               + __popc(tr[82] ^ wt[3]) + __popc(tr[83] ^ wt[4])
               + __popc(tr[110] ^ wt[6]) + __popc(tr[111] ^ wt[7]);
        int d0 = madin2(a0, Cr0), d1 = madin2(a1, Cr1);
        nb1 = sgn ? (max(d0, d1) >= T) : (min(d0, d1) <= T);
    }
    bal = __ballot_sync(0xffffffffu, nb0 | nb1);
    if (lane == 0) outp[26] = bal;
#undef C2_INT
}

// ---------------- block2: warp/(img,row,half), lane = channel, CSA popc ----------------
__global__ void __launch_bounds__(256, 4) conv3_kernel() {
    __shared__ unsigned long long stile[4][4][14];
    int tid = threadIdx.x;
    int U0 = blockIdx.x * 4;
    for (int i = tid; i < 224; i += 256) {
        int u = i / 56, r = i % 56, j = r / 14, col = r % 14;
        int U = U0 + u, b = U / 7, oy = U % 7;
        int ir = 2 * oy - 1 + j;
        stile[u][j][col] = (ir >= 0 && ir < 14) ? g_h2[b * 196 + ir * 14 + col] : 0ull;
    }
    __syncthreads();

    int w = tid >> 5, lane = tid & 31;
    int u = w >> 1, h = w & 1;
    int U = U0 + u, b = U / 7, oy = U % 7;
    int c = h * 32 + lane;

    unsigned long long wt[9];
#pragma unroll
    for (int t = 0; t < 9; t++) wt[t] = g_w3p[c * 10 + t];

    bool e0 = (oy == 0), e1 = (oy == 6);
    int v0 = e0 ? 2 : 3, v1 = e1 ? 2 : 3;
    int pw0 = __popcll(wt[0]), pw1 = __popcll(wt[1]), pw2 = __popcll(wt[2]);
    int pw6 = __popcll(wt[6]), pw7 = __popcll(wt[7]), pw8 = __popcll(wt[8]);
    int Ci0 = 192 * v0 + (e0 ? 2 * (pw0 + pw1 + pw2) : 0);
    int Ci1 = 192 * v1 + (e1 ? 2 * (pw6 + pw7 + pw8) : 0);
    int Cl0 = 128 * v0 + (e0 ? 2 * (pw1 + pw2) : 0);
    int Cl1 = 128 * v1 + (e1 ? 2 * (pw7 + pw8) : 0);
    int Cr0 = 128 * v0 + (e0 ? 2 * (pw0 + pw1) : 0);
    int Cr1 = 128 * v1 + (e1 ? 2 * (pw6 + pw7) : 0);

    int2 th = g_th3[c];
    int T = th.x;
    bool sgn = th.y != 0;
    const unsigned long long* tr = &stile[u][0][0];
    uint32_t* outp = g_h3u + (b * 49 + oy * 7) * 2 + h;

#define C3_INT(X, nb) { \
    unsigned long long r0a = tr[(X)-1],    r0b = tr[(X)],    r0c = tr[(X)+1]; \
    unsigned long long r1a = tr[14+(X)-1], r1b = tr[14+(X)], r1c = tr[14+(X)+1]; \
    unsigned long long r2a = tr[28+(X)-1], r2b = tr[28+(X)], r2c = tr[28+(X)+1]; \
    unsigned long long r3a = tr[42+(X)-1], r3b = tr[42+(X)], r3c = tr[42+(X)+1]; \
    int a0, a1; \
    POP9_64(a0, r0a^wt[0], r0b^wt[1], r0c^wt[2], r1a^wt[3], r1b^wt[4], r1c^wt[5], \
                r2a^wt[6], r2b^wt[7], r2c^wt[8]); \
    POP9_64(a1, r1a^wt[0], r1b^wt[1], r1c^wt[2], r2a^wt[3], r2b^wt[4], r2c^wt[5], \
                r3a^wt[6], r3b^wt[7], r3c^wt[8]); \
    int d0 = madin2(a0, Ci0), d1 = madin2(a1, Ci1); \
    nb = sgn ? (max(d0, d1) >= T) : (min(d0, d1) <= T); }

    bool nb0, nb1;
    {   // X = 0 edge
        int a0 = __popcll(tr[0] ^ wt[1]) + __popcll(tr[1] ^ wt[2])
               + __popcll(tr[14] ^ wt[4]) + __popcll(tr[15] ^ wt[5])
               + __popcll(tr[28] ^ wt[7]) + __popcll(tr[29] ^ wt[8]);
        int a1 = __popcll(tr[14] ^ wt[1]) + __popcll(tr[15] ^ wt[2])
               + __popcll(tr[28] ^ wt[4]) + __popcll(tr[29] ^ wt[5])
               + __popcll(tr[42] ^ wt[7]) + __popcll(tr[43] ^ wt[8]);
        int d0 = madin2(a0, Cl0), d1 = madin2(a1, Cl1);
        nb0 = sgn ? (max(d0, d1) >= T) : (min(d0, d1) <= T);
    }
    C3_INT(1, nb1);
    uint32_t bal = __ballot_sync(0xffffffffu, nb0 | nb1);
    if (lane == 0) outp[0] = bal;

#pragma unroll 2
    for (int ox = 1; ox <= 5; ox++) {
        C3_INT(2 * ox, nb0);
        C3_INT(2 * ox + 1, nb1);
        bal = __ballot_sync(0xffffffffu, nb0 | nb1);
        if (lane == 0) outp[2 * ox] = bal;
    }

    C3_INT(12, nb0);
    {   // X = 13 edge
        int a0 = __popcll(tr[12] ^ wt[0]) + __popcll(tr[13] ^ wt[1])
               + __popcll(tr[26] ^ wt[3]) + __popcll(tr[27] ^ wt[4])
               + __popcll(tr[40] ^ wt[6]) + __popcll(tr[41] ^ wt[7]);
        int a1 = __popcll(tr[26] ^ wt[0]) + __popcll(tr[27] ^ wt[1])
               + __popcll(tr[40] ^ wt[3]) + __popcll(tr[41] ^ wt[4])
               + __popcll(tr[54] ^ wt[6]) + __popcll(tr[55] ^ wt[7]);
        int d0 = madin2(a0, Cr0), d1 = madin2(a1, Cr1);
        nb1 = sgn ? (max(d0, d1) >= T) : (min(d0, d1) <= T);
    }
    bal = __ballot_sync(0xffffffffu, nb0 | nb1);
    if (lane == 0) outp[12] = bal;
#undef C3_INT
}

// ---------------- classifier: w_fc cached in smem, FC_IMGS images per block ----------------
__global__ void __launch_bounds__(256) fc_kernel(const float* __restrict__ w_head,
                                                 const float* __restrict__ b_head,
                                                 float* __restrict__ out) {
    extern __shared__ char fsm[];
    unsigned long long* swfc = (unsigned long long*)fsm;        // 12544 u64 = 100352 B
    float* swh = (float*)(fsm + 100352);                        // 2560 floats = 10240 B
    __shared__ unsigned long long xrow[49];
    __shared__ float h4[256];
    int t = threadIdx.x;

    for (int i = t; i < 12544; i += 256) swfc[i] = g_wfcp[i];
    for (int i = t; i < 2560; i += 256) swh[i] = w_head[i];
    float4 bn = g_bn4[t];
    const unsigned long long* wr = swfc + t * 49;
    __syncthreads();

    for (int k = 0; k < FC_IMGS; k++) {
        int b = blockIdx.x * FC_IMGS + k;
        if (b >= BATCH) break;                          // uniform across block
        if (t < 49) {
            uint32_t lo = g_h3u[(b * 49 + t) * 2];
            uint32_t hi = g_h3u[(b * 49 + t) * 2 + 1];
            xrow[t] = (unsigned long long)lo | ((unsigned long long)hi << 32);
        }
        __syncthreads();

        int acc = 0;
#pragma unroll
        for (int p = 0; p < 49; p++) acc += __popcll(xrow[p] ^ wr[p]);
        h4[t] = ((float)(3136 - 2 * acc) - bn.y) * bn.x + bn.z;
        __syncthreads();

        if (t < 10) {
            float s = b_head[t];
            const float* wh = swh + t * 256;
#pragma unroll 8
            for (int c = 0; c < 256; c++) s += h4[c] * wh[c];
            out[b * 10 + t] = s;
        }
        __syncthreads();
    }
}

// ---------------- launch ----------------
extern "C" void kernel_launch(void* const* d_in, const int* in_sizes, int n_in,
                              void* d_out, int out_size) {
    const float* x      = (const float*)d_in[0];
    const float* w_stem = (const float*)d_in[1];
    const float* g1 = (const float*)d_in[2];
    const float* b1 = (const float*)d_in[3];
    const float* m1 = (const float*)d_in[4];
    const float* v1 = (const float*)d_in[5];
    const float* w2 = (const float*)d_in[6];
    const float* g2 = (const float*)d_in[7];
    const float* b2 = (const float*)d_in[8];
    const float* m2 = (const float*)d_in[9];
    const float* v2 = (const float*)d_in[10];
    const float* w3 = (const float*)d_in[11];
    const float* g3 = (const float*)d_in[12];
    const float* b3 = (const float*)d_in[13];
    const float* m3 = (const float*)d_in[14];
    const float* v3 = (const float*)d_in[15];
    const float* w_fc = (const float*)d_in[16];
    const float* g4 = (const float*)d_in[17];
    const float* b4 = (const float*)d_in[18];
    const float* m4 = (const float*)d_in[19];
    const float* v4 = (const float*)d_in[20];
    const float* w_head = (const float*)d_in[21];
    const float* b_head = (const float*)d_in[22];
    float* out = (float*)d_out;

    const int fc_smem = 100352 + 10240;
    cudaFuncSetAttribute(fc_kernel, cudaFuncAttributeMaxDynamicSharedMemorySize, fc_smem);

    stem_pack_kernel<<<BATCH * 4 + 65, 224>>>(x, w_stem, w2, w3, w_fc,
                                              g1, v1, m1, b1, g2, v2, m2, b2,
                                              g3, v3, m3, b3, g4, v4, m4, b4);
    conv2_kernel<<<(BATCH * 14) / 4, 256>>>();       // 7168 blocks
    conv3_kernel<<<(BATCH * 7) / 4, 256>>>();        // 3584 blocks
    fc_kernel<<<FC_BLOCKS, 256, fc_smem>>>(w_head, b_head, out);
}

// round 17
// speedup vs baseline: 2.1826x; 1.1018x over previous
#include <cuda_runtime.h>
#include <stdint.h>

#define BATCH 2048
#define EPS 1e-5f

// ---------------- static scratch ----------------
__device__ uint32_t           g_h1[BATCH * 784];        // stem out, 32 ch packed
__device__ unsigned long long g_h2[BATCH * 196];        // block1 out, 64 ch packed (u32 halves)
__device__ uint32_t           g_h3u[BATCH * 49 * 2];    // block2 out, u32 halves
__device__ uint32_t           g_w2p[64 * 12];           // sign(w2), [ch][tap] stride 12
__device__ unsigned long long g_w3p[64 * 10];           // sign(w3), [ch][tap] stride 10
__device__ unsigned long long g_wfcp[256 * 49];         // sign(w_fc)
__device__ float4 g_bn4[256];                           // (inv, mean, beta, 0)
__device__ int2   g_th2[64], g_th3[64];                 // (integer threshold, sgn)

// IMAD helpers: force mad.lo.s32 so the adds dispatch to the FMA pipe
__device__ __forceinline__ int madi2(int a, int b) {
    int r; asm("mad.lo.s32 %0, %1, 2, %2;" : "=r"(r) : "r"(a), "r"(b)); return r;
}
__device__ __forceinline__ int madi4(int a, int b) {
    int r; asm("mad.lo.s32 %0, %1, 4, %2;" : "=r"(r) : "r"(a), "r"(b)); return r;
}
__device__ __forceinline__ int madin2(int a, int b) {
    int r; asm("mad.lo.s32 %0, %1, -2, %2;" : "=r"(r) : "r"(a), "r"(b)); return r;
}

// carry-save adder compressors (single LOP3 each after ptxas fusion)
#define CSA32(s, c, x, y, z) do { uint32_t _x = (x), _y = (y), _z = (z); \
    (s) = _x ^ _y ^ _z; (c) = (_x & _y) | (_z & (_x | _y)); } while (0)
#define CSA64(s, c, x, y, z) do { unsigned long long _x = (x), _y = (y), _z = (z); \
    (s) = _x ^ _y ^ _z; (c) = (_x & _y) | (_z & (_x | _y)); } while (0)

// popcount of sum of 9 words via full CSA tree: 4 POPC + IMAD chain
#define POP9_32(res, v0, v1, v2, v3, v4, v5, v6, v7, v8) do { \
    uint32_t _s1, _c1, _s2, _c2, _s3, _c3, _s4, _c4, _s5, _c5; \
    CSA32(_s1, _c1, v0, v1, v2); CSA32(_s2, _c2, v3, v4, v5); CSA32(_s3, _c3, v6, v7, v8); \
    CSA32(_s4, _c4, _s1, _s2, _s3); CSA32(_s5, _c5, _c1, _c2, _c3); \
    (res) = madi2(__popc(_c4), madi2(__popc(_s5), madi4(__popc(_c5), __popc(_s4)))); } while (0)
#define POP9_64(res, v0, v1, v2, v3, v4, v5, v6, v7, v8) do { \
    unsigned long long _s1, _c1, _s2, _c2, _s3, _c3, _s4, _c4, _s5, _c5; \
    CSA64(_s1, _c1, v0, v1, v2); CSA64(_s2, _c2, v3, v4, v5); CSA64(_s3, _c3, v6, v7, v8); \
    CSA64(_s4, _c4, _s1, _s2, _s3); CSA64(_s5, _c5, _c1, _c2, _c3); \
    (res) = madi2(__popcll(_c4), madi2(__popcll(_s5), madi4(__popcll(_c5), __popcll(_s4)))); } while (0)

// ---------------- stem (warp per row, lane = channel) + merged pack ----------------
__global__ void __launch_bounds__(224) stem_pack_kernel(
        const float* __restrict__ x, const float* __restrict__ ws,
        const float* __restrict__ w2, const float* __restrict__ w3,
        const float* __restrict__ wfc,
        const float* __restrict__ g1, const float* __restrict__ v1,
        const float* __restrict__ m1, const float* __restrict__ b1,
        const float* __restrict__ g2, const float* __restrict__ v2,
        const float* __restrict__ m2, const float* __restrict__ b2,
        const float* __restrict__ g3, const float* __restrict__ v3,
        const float* __restrict__ m3, const float* __restrict__ b3,
        const float* __restrict__ g4, const float* __restrict__ v4,
        const float* __restrict__ m4, const float* __restrict__ b4) {
    int tid = threadIdx.x;

    if (blockIdx.x >= BATCH * 4) {                     // ---- pack branch ----
        int idx = (blockIdx.x - BATCH * 4) * 224 + tid;
        if (idx < 768) {                               // w2: [64,32,3,3] -> stride 12
            int o = idx / 12, t = idx % 12;
            uint32_t bits = 0;
            if (t < 9)
                for (int c = 0; c < 32; c++)
                    bits |= (w2[o * 288 + c * 9 + t] >= 0.f ? 1u : 0u) << c;
            g_w2p[idx] = bits;
        } else if (idx < 1408) {                       // w3: [64,64,3,3] -> stride 10
            int j = idx - 768; int o = j / 10, t = j % 10;
            unsigned long long bits = 0;
            if (t < 9)
                for (int c = 0; c < 64; c++)
                    bits |= (unsigned long long)(w3[o * 576 + c * 9 + t] >= 0.f) << c;
            g_w3p[j] = bits;
        } else if (idx < 13952) {                      // w_fc: [256,3136]
            int j = idx - 1408; int o = j / 49, p = j % 49;
            unsigned long long bits = 0;
            for (int c = 0; c < 64; c++)
                bits |= (unsigned long long)(wfc[o * 3136 + c * 49 + p] >= 0.f) << c;
            g_wfcp[j] = bits;
        } else if (idx < 14208) {
            int c = idx - 13952;
            g_bn4[c] = make_float4(g4[c] / sqrtf(v4[c] + EPS), m4[c], b4[c], 0.f);
        } else if (idx < 14272) {                      // conv2 thresholds
            int c = idx - 14208;
            float inv = g2[c] / sqrtf(v2[c] + EPS), m = m2[c], be = b2[c];
            int sgn = (inv >= 0.f) ? 1 : 0;
            int T;
            if (sgn) {
                T = 10000;
                for (int d = -288; d <= 288; d += 2)
                    if (((float)d - m) * inv + be >= 0.f) { T = d; break; }
            } else {
                T = -10000;
                for (int d = 288; d >= -288; d -= 2)
                    if (((float)d - m) * inv + be >= 0.f) { T = d; break; }
            }
            g_th2[c] = make_int2(T, sgn);
        } else if (idx < 14336) {                      // conv3 thresholds
            int c = idx - 14272;
            float inv = g3[c] / sqrtf(v3[c] + EPS), m = m3[c], be = b3[c];
            int sgn = (inv >= 0.f) ? 1 : 0;
            int T;
            if (sgn) {
                T = 10000;
                for (int d = -576; d <= 576; d += 2)
                    if (((float)d - m) * inv + be >= 0.f) { T = d; break; }
            } else {
                T = -10000;
                for (int d = 576; d >= -576; d -= 2)
                    if (((float)d - m) * inv + be >= 0.f) { T = d; break; }
            }
            g_th3[c] = make_int2(T, sgn);
        }
        return;
    }

    // ---- stem branch ----
    __shared__ float tile[9][32];
    int img = blockIdx.x >> 2, q = blockIdx.x & 3;
    int y0 = q * 7;
    const float* xb = x + img * 784;

    for (int i = tid; i < 270; i += 224) {
        int r = i / 30, col = i % 30;
        int yy = y0 - 1 + r, xc = col - 1;
        float v = 0.f;
        if (yy >= 0 && yy < 28 && xc >= 0 && xc < 28) v = xb[yy * 28 + xc];
        tile[r][col] = v;
    }

    int wid = tid >> 5, lane = tid & 31;
    float wt[9];
#pragma unroll
    for (int k = 0; k < 9; k++) wt[k] = ws[lane * 9 + k];
    float bnx = g1[lane] / sqrtf(v1[lane] + EPS);
    float bny = m1[lane], bnz = b1[lane];
    __syncthreads();

    int y = y0 + wid;
    uint32_t* orow = g_h1 + img * 784 + y * 28;

    float p0 = tile[wid][0],     p1 = tile[wid + 1][0],     p2 = tile[wid + 2][0];
    float q0 = tile[wid][1],     q1 = tile[wid + 1][1],     q2 = tile[wid + 2][1];

#pragma unroll
    for (int xx = 0; xx < 28; xx++) {
        float r0 = tile[wid][xx + 2], r1 = tile[wid + 1][xx + 2], r2 = tile[wid + 2][xx + 2];
        float s = wt[0] * p0;
        s += wt[1] * q0;  s += wt[2] * r0;
        s += wt[3] * p1;  s += wt[4] * q1;  s += wt[5] * r1;
        s += wt[6] * p2;  s += wt[7] * q2;  s += wt[8] * r2;
        float v = (s - bny) * bnx + bnz;
        uint32_t bits = __ballot_sync(0xffffffffu, v >= 0.f);
        if (lane == 0) orow[xx] = bits;
        p0 = q0; p1 = q1; p2 = q2;
        q0 = r0; q1 = r1; q2 = r2;
    }
}

// ---------------- block1: warp/(img,row,half), lane = channel, CSA popc ----------------
__global__ void __launch_bounds__(256, 4) conv2_kernel() {
    __shared__ uint32_t stile[4][4][28];
    int tid = threadIdx.x;
    int U0 = blockIdx.x * 4;
    for (int i = tid; i < 448; i += 256) {
        int u = i / 112, r = i % 112, j = r / 28, col = r % 28;
        int U = U0 + u, b = U / 14, oy = U % 14;
        int ir = 2 * oy - 1 + j;
        stile[u][j][col] = (ir >= 0 && ir < 28) ? g_h1[b * 784 + ir * 28 + col] : 0u;
    }
    __syncthreads();

    int w = tid >> 5, lane = tid & 31;
    int u = w >> 1, h = w & 1;
    int U = U0 + u, b = U / 14, oy = U % 14;
    int c = h * 32 + lane;

    uint32_t wt[9];
#pragma unroll
    for (int t = 0; t < 9; t++) wt[t] = g_w2p[c * 12 + t];

    bool e0 = (oy == 0), e1 = (oy == 13);
    int v0 = e0 ? 2 : 3, v1 = e1 ? 2 : 3;
    int pw0 = __popc(wt[0]), pw1 = __popc(wt[1]), pw2 = __popc(wt[2]);
    int pw6 = __popc(wt[6]), pw7 = __popc(wt[7]), pw8 = __popc(wt[8]);
    int Ci0 = 96 * v0 + (e0 ? 2 * (pw0 + pw1 + pw2) : 0);
    int Ci1 = 96 * v1 + (e1 ? 2 * (pw6 + pw7 + pw8) : 0);
    int Cl0 = 64 * v0 + (e0 ? 2 * (pw1 + pw2) : 0);
    int Cl1 = 64 * v1 + (e1 ? 2 * (pw7 + pw8) : 0);
    int Cr0 = 64 * v0 + (e0 ? 2 * (pw0 + pw1) : 0);
    int Cr1 = 64 * v1 + (e1 ? 2 * (pw6 + pw7) : 0);

    int2 th = g_th2[c];
    int T = th.x;
    bool sgn = th.y != 0;
    const uint32_t* tr = &stile[u][0][0];
    uint32_t* outp = ((uint32_t*)g_h2) + (b * 196 + oy * 14) * 2 + h;

#define C2_INT(X, nb) { \
    uint32_t r0a = tr[(X)-1],    r0b = tr[(X)],    r0c = tr[(X)+1]; \
    uint32_t r1a = tr[28+(X)-1], r1b = tr[28+(X)], r1c = tr[28+(X)+1]; \
    uint32_t r2a = tr[56+(X)-1], r2b = tr[56+(X)], r2c = tr[56+(X)+1]; \
    uint32_t r3a = tr[84+(X)-1], r3b = tr[84+(X)], r3c = tr[84+(X)+1]; \
    int a0, a1; \
    POP9_32(a0, r0a^wt[0], r0b^wt[1], r0c^wt[2], r1a^wt[3], r1b^wt[4], r1c^wt[5], \
                r2a^wt[6], r2b^wt[7], r2c^wt[8]); \
    POP9_32(a1, r1a^wt[0], r1b^wt[1], r1c^wt[2], r2a^wt[3], r2b^wt[4], r2c^wt[5], \
                r3a^wt[6], r3b^wt[7], r3c^wt[8]); \
    int d0 = madin2(a0, Ci0), d1 = madin2(a1, Ci1); \
    nb = sgn ? (max(d0, d1) >= T) : (min(d0, d1) <= T); }

    bool nb0, nb1;
    {   // X = 0 edge
        int a0 = __popc(tr[0] ^ wt[1]) + __popc(tr[1] ^ wt[2])
               + __popc(tr[28] ^ wt[4]) + __popc(tr[29] ^ wt[5])
               + __popc(tr[56] ^ wt[7]) + __popc(tr[57] ^ wt[8]);
        int a1 = __popc(tr[28] ^ wt[1]) + __popc(tr[29] ^ wt[2])
               + __popc(tr[56] ^ wt[4]) + __popc(tr[57] ^ wt[5])
               + __popc(tr[84] ^ wt[7]) + __popc(tr[85] ^ wt[8]);
        int d0 = madin2(a0, Cl0), d1 = madin2(a1, Cl1);
        nb0 = sgn ? (max(d0, d1) >= T) : (min(d0, d1) <= T);
    }
    C2_INT(1, nb1);
    uint32_t bal = __ballot_sync(0xffffffffu, nb0 | nb1);
    if (lane == 0) outp[0] = bal;

#pragma unroll 2
    for (int ox = 1; ox <= 12; ox++) {
        C2_INT(2 * ox, nb0);
        C2_INT(2 * ox + 1, nb1);
        bal = __ballot_sync(0xffffffffu, nb0 | nb1);
        if (lane == 0) outp[2 * ox] = bal;
    }

    C2_INT(26, nb0);
    {   // X = 27 edge
        int a0 = __popc(tr[26] ^ wt[0]) + __popc(tr[27] ^ wt[1])
               + __popc(tr[54] ^ wt[3]) + __popc(tr[55] ^ wt[4])
               + __popc(tr[82] ^ wt[6]) + __popc(tr[83] ^ wt[7]);
        int a1 = __popc(tr[54] ^ wt[0]) + __popc(tr[55] ^ wt[1])
               + __popc(tr[82] ^ wt[3]) + __popc(tr[83] ^ wt[4])
               + __popc(tr[110] ^ wt[6]) + __popc(tr[111] ^ wt[7]);
        int d0 = madin2(a0, Cr0), d1 = madin2(a1, Cr1);
        nb1 = sgn ? (max(d0, d1) >= T) : (min(d0, d1) <= T);
    }
    bal = __ballot_sync(0xffffffffu, nb0 | nb1);
    if (lane == 0) outp[26] = bal;
#undef C2_INT
}

// ---------------- block2: warp/(img,row,half), lane = channel, CSA popc ----------------
__global__ void __launch_bounds__(256, 4) conv3_kernel() {
    __shared__ unsigned long long stile[4][4][14];
    int tid = threadIdx.x;
    int U0 = blockIdx.x * 4;
    for (int i = tid; i < 224; i += 256) {
        int u = i / 56, r = i % 56, j = r / 14, col = r % 14;
        int U = U0 + u, b = U / 7, oy = U % 7;
        int ir = 2 * oy - 1 + j;
        stile[u][j][col] = (ir >= 0 && ir < 14) ? g_h2[b * 196 + ir * 14 + col] : 0ull;
    }
    __syncthreads();

    int w = tid >> 5, lane = tid & 31;
    int u = w >> 1, h = w & 1;
    int U = U0 + u, b = U / 7, oy = U % 7;
    int c = h * 32 + lane;

    unsigned long long wt[9];
#pragma unroll
    for (int t = 0; t < 9; t++) wt[t] = g_w3p[c * 10 + t];

    bool e0 = (oy == 0), e1 = (oy == 6);
    int v0 = e0 ? 2 : 3, v1 = e1 ? 2 : 3;
    int pw0 = __popcll(wt[0]), pw1 = __popcll(wt[1]), pw2 = __popcll(wt[2]);
    int pw6 = __popcll(wt[6]), pw7 = __popcll(wt[7]), pw8 = __popcll(wt[8]);
    int Ci0 = 192 * v0 + (e0 ? 2 * (pw0 + pw1 + pw2) : 0);
    int Ci1 = 192 * v1 + (e1 ? 2 * (pw6 + pw7 + pw8) : 0);
    int Cl0 = 128 * v0 + (e0 ? 2 * (pw1 + pw2) : 0);
    int Cl1 = 128 * v1 + (e1 ? 2 * (pw7 + pw8) : 0);
    int Cr0 = 128 * v0 + (e0 ? 2 * (pw0 + pw1) : 0);
    int Cr1 = 128 * v1 + (e1 ? 2 * (pw6 + pw7) : 0);

    int2 th = g_th3[c];
    int T = th.x;
    bool sgn = th.y != 0;
    const unsigned long long* tr = &stile[u][0][0];
    uint32_t* outp = g_h3u + (b * 49 + oy * 7) * 2 + h;

#define C3_INT(X, nb) { \
    unsigned long long r0a = tr[(X)-1],    r0b = tr[(X)],    r0c = tr[(X)+1]; \
    unsigned long long r1a = tr[14+(X)-1], r1b = tr[14+(X)], r1c = tr[14+(X)+1]; \
    unsigned long long r2a = tr[28+(X)-1], r2b = tr[28+(X)], r2c = tr[28+(X)+1]; \
    unsigned long long r3a = tr[42+(X)-1], r3b = tr[42+(X)], r3c = tr[42+(X)+1]; \
    int a0, a1; \
    POP9_64(a0, r0a^wt[0], r0b^wt[1], r0c^wt[2], r1a^wt[3], r1b^wt[4], r1c^wt[5], \
                r2a^wt[6], r2b^wt[7], r2c^wt[8]); \
    POP9_64(a1, r1a^wt[0], r1b^wt[1], r1c^wt[2], r2a^wt[3], r2b^wt[4], r2c^wt[5], \
                r3a^wt[6], r3b^wt[7], r3c^wt[8]); \
    int d0 = madin2(a0, Ci0), d1 = madin2(a1, Ci1); \
    nb = sgn ? (max(d0, d1) >= T) : (min(d0, d1) <= T); }

    bool nb0, nb1;
    {   // X = 0 edge
        int a0 = __popcll(tr[0] ^ wt[1]) + __popcll(tr[1] ^ wt[2])
               + __popcll(tr[14] ^ wt[4]) + __popcll(tr[15] ^ wt[5])
               + __popcll(tr[28] ^ wt[7]) + __popcll(tr[29] ^ wt[8]);
        int a1 = __popcll(tr[14] ^ wt[1]) + __popcll(tr[15] ^ wt[2])
               + __popcll(tr[28] ^ wt[4]) + __popcll(tr[29] ^ wt[5])
               + __popcll(tr[42] ^ wt[7]) + __popcll(tr[43] ^ wt[8]);
        int d0 = madin2(a0, Cl0), d1 = madin2(a1, Cl1);
        nb0 = sgn ? (max(d0, d1) >= T) : (min(d0, d1) <= T);
    }
    C3_INT(1, nb1);
    uint32_t bal = __ballot_sync(0xffffffffu, nb0 | nb1);
    if (lane == 0) outp[0] = bal;

#pragma unroll 2
    for (int ox = 1; ox <= 5; ox++) {
        C3_INT(2 * ox, nb0);
        C3_INT(2 * ox + 1, nb1);
        bal = __ballot_sync(0xffffffffu, nb0 | nb1);
        if (lane == 0) outp[2 * ox] = bal;
    }

    C3_INT(12, nb0);
    {   // X = 13 edge
        int a0 = __popcll(tr[12] ^ wt[0]) + __popcll(tr[13] ^ wt[1])
               + __popcll(tr[26] ^ wt[3]) + __popcll(tr[27] ^ wt[4])
               + __popcll(tr[40] ^ wt[6]) + __popcll(tr[41] ^ wt[7]);
        int a1 = __popcll(tr[26] ^ wt[0]) + __popcll(tr[27] ^ wt[1])
               + __popcll(tr[40] ^ wt[3]) + __popcll(tr[41] ^ wt[4])
               + __popcll(tr[54] ^ wt[6]) + __popcll(tr[55] ^ wt[7]);
        int d0 = madin2(a0, Cr0), d1 = madin2(a1, Cr1);
        nb1 = sgn ? (max(d0, d1) >= T) : (min(d0, d1) <= T);
    }
    bal = __ballot_sync(0xffffffffu, nb0 | nb1);
    if (lane == 0) outp[12] = bal;
#undef C3_INT
}

// ---------------- classifier: warp per image, smem-cached weights ----------------
// 128 blocks x 512 threads (16 warps); warp w -> image blockIdx.x*16 + w
__global__ void __launch_bounds__(512) fc_kernel(const float* __restrict__ w_head,
                                                 const float* __restrict__ b_head,
                                                 float* __restrict__ out) {
    extern __shared__ char fsm[];
    unsigned long long* swfc = (unsigned long long*)fsm;        // 12544 u64 = 100352 B
    float* swh = (float*)(fsm + 100352);                        // 2560 floats = 10240 B
    unsigned long long* xr = (unsigned long long*)(fsm + 110592);  // [16][50] u64
    int t = threadIdx.x;
    int w = t >> 5, lane = t & 31;

    for (int i = t; i < 12544; i += 512) swfc[i] = g_wfcp[i];
    for (int i = t; i < 2560; i += 512) swh[i] = w_head[i];
    __syncthreads();

    int b = blockIdx.x * 16 + w;
    unsigned long long* xrow = xr + w * 50;

    // stage this image's 49 words into warp-private smem
    if (lane < 25) {
        int p0 = lane;
        uint32_t lo = g_h3u[(b * 49 + p0) * 2 - (p0 == 49 ? 2 : 0)];
        (void)lo;
    }
    // simple: two strided passes
    {
        int p = lane;
        if (p < 49) {
            uint32_t lo = g_h3u[(b * 49 + p) * 2];
            uint32_t hi = g_h3u[(b * 49 + p) * 2 + 1];
            xrow[p] = (unsigned long long)lo | ((unsigned long long)hi << 32);
        }
        p = lane + 32;
        if (p < 49) {
            uint32_t lo = g_h3u[(b * 49 + p) * 2];
            uint32_t hi = g_h3u[(b * 49 + p) * 2 + 1];
            xrow[p] = (unsigned long long)lo | ((unsigned long long)hi << 32);
        }
    }
    __syncwarp();

    // each lane: 8 channels c = k*32 + lane
    float h4v[8];
#pragma unroll
    for (int k = 0; k < 8; k++) {
        int c = k * 32 + lane;
        const unsigned long long* wr = swfc + c * 49;
        int acc = 0;
#pragma unroll
        for (int p = 0; p < 49; p++) acc += __popcll(xrow[p] ^ wr[p]);
        float4 bn = g_bn4[c];
        h4v[k] = ((float)(3136 - 2 * acc) - bn.y) * bn.x + bn.z;
    }

    // head: 10 logits via per-lane partial + warp butterfly reduction
#pragma unroll
    for (int j = 0; j < 10; j++) {
        float s = 0.f;
#pragma unroll
        for (int k = 0; k < 8; k++) s += h4v[k] * swh[j * 256 + k * 32 + lane];
        s += __shfl_xor_sync(0xffffffffu, s, 16);
        s += __shfl_xor_sync(0xffffffffu, s, 8);
        s += __shfl_xor_sync(0xffffffffu, s, 4);
        s += __shfl_xor_sync(0xffffffffu, s, 2);
        s += __shfl_xor_sync(0xffffffffu, s, 1);
        if (lane == 0) out[b * 10 + j] = s + b_head[j];
    }
}

// ---------------- launch ----------------
extern "C" void kernel_launch(void* const* d_in, const int* in_sizes, int n_in,
                              void* d_out, int out_size) {
    const float* x      = (const float*)d_in[0];
    const float* w_stem = (const float*)d_in[1];
    const float* g1 = (const float*)d_in[2];
    const float* b1 = (const float*)d_in[3];
    const float* m1 = (const float*)d_in[4];
    const float* v1 = (const float*)d_in[5];
    const float* w2 = (const float*)d_in[6];
    const float* g2 = (const float*)d_in[7];
    const float* b2 = (const float*)d_in[8];
    const float* m2 = (const float*)d_in[9];
    const float* v2 = (const float*)d_in[10];
    const float* w3 = (const float*)d_in[11];
    const float* g3 = (const float*)d_in[12];
    const float* b3 = (const float*)d_in[13];
    const float* m3 = (const float*)d_in[14];
    const float* v3 = (const float*)d_in[15];
    const float* w_fc = (const float*)d_in[16];
    const float* g4 = (const float*)d_in[17];
    const float* b4 = (const float*)d_in[18];
    const float* m4 = (const float*)d_in[19];
    const float* v4 = (const float*)d_in[20];
    const float* w_head = (const float*)d_in[21];
    const float* b_head = (const float*)d_in[22];
    float* out = (float*)d_out;

    const int fc_smem = 100352 + 10240 + 16 * 50 * 8;   // 116992 B
    cudaFuncSetAttribute(fc_kernel, cudaFuncAttributeMaxDynamicSharedMemorySize, fc_smem);

    stem_pack_kernel<<<BATCH * 4 + 65, 224>>>(x, w_stem, w2, w3, w_fc,
                                              g1, v1, m1, b1, g2, v2, m2, b2,
                                              g3, v3, m3, b3, g4, v4, m4, b4);
    conv2_kernel<<<(BATCH * 14) / 4, 256>>>();       // 7168 blocks
    conv3_kernel<<<(BATCH * 7) / 4, 256>>>();        // 3584 blocks
    fc_kernel<<<BATCH / 16, 512, fc_smem>>>(w_head, b_head, out);
}